// round 14
// baseline (speedup 1.0000x reference)
#include <cuda_runtime.h>
#include <cuda_fp16.h>
#include <cstdint>
#include <math.h>

#define T_TOK 2048
#define H_DIM 2048
#define S_LEN 1024
#define E_NUM 16
#define I_DIM 1408
#define TWO_I 2816
#define SHI_DIM 2816
#define SH2 5632

// ---------------- fp32 scratch ----------------
__device__ float g_hid [(size_t)T_TOK * H_DIM];
__device__ int   g_cnt [E_NUM];
__device__ int   g_tok [E_NUM * T_TOK];
__device__ int   g_texp[T_TOK * 4];
__device__ int   g_trow[T_TOK * 4];
__device__ float g_twt [T_TOK * 4];

// ---------------- fp16 planes ----------------
__device__ __half c_Xh  [(size_t)T_TOK * H_DIM];
__device__ __half c_qkvo[(size_t)T_TOK * 6144];
__device__ __half c_ath [(size_t)T_TOK * 2048];
__device__ __half c_X2h [(size_t)T_TOK * H_DIM];
__device__ __half c_guh [(size_t)E_NUM * T_TOK * I_DIM];
__device__ __half c_sah [(size_t)T_TOK * SHI_DIM];
__device__ __half c_down[(size_t)E_NUM * T_TOK * H_DIM];
__device__ __half c_qkvw[(size_t)6144 * 2048];
__device__ __half c_owh [(size_t)2048 * 2048];
__device__ __half c_w1h [(size_t)E_NUM * TWO_I * H_DIM];
__device__ __half c_w2h [(size_t)E_NUM * H_DIM * I_DIM];
__device__ __half c_sgh [(size_t)SH2 * H_DIM];
__device__ __half c_sdh [(size_t)H_DIM * SHI_DIM];

// ================= helpers =================
static __device__ __forceinline__ uint32_t smem_u32(const void* p) {
    uint32_t a;
    asm("{ .reg .u64 t; cvta.to.shared.u64 t, %1; cvt.u32.u64 %0, t; }" : "=r"(a) : "l"(p));
    return a;
}
static __device__ __forceinline__ uint32_t h2only(float x, float y) {
    __half2 hp = __halves2half2(__float2half_rn(x), __float2half_rn(y));
    return *(uint32_t*)&hp;
}
__device__ __forceinline__ float silu_f(float x) { return x / (1.0f + __expf(-x)); }
#define LDM4(r, a) \
    asm volatile("ldmatrix.sync.aligned.m8n8.x4.shared.b16 {%0,%1,%2,%3}, [%4];" \
        : "=r"((r)[0]), "=r"((r)[1]), "=r"((r)[2]), "=r"((r)[3]) : "r"(a))
#define MMAF32(c, a, b0, b1) \
    asm volatile("mma.sync.aligned.m16n8k16.row.col.f32.f16.f16.f32 " \
        "{%0,%1,%2,%3}, {%4,%5,%6,%7}, {%8,%9}, {%0,%1,%2,%3};" \
        : "+f"((c)[0]), "+f"((c)[1]), "+f"((c)[2]), "+f"((c)[3]) \
        : "r"((a)[0]), "r"((a)[1]), "r"((a)[2]), "r"((a)[3]), "r"(b0), "r"(b1))
#define CPA16(d, s, n) \
    asm volatile("cp.async.cg.shared.global [%0], [%1], 16, %2;" :: "r"(d), "l"(s), "r"(n) : "memory")
#define CPA_COMMIT() asm volatile("cp.async.commit_group;" ::: "memory")
#define CPA_WAIT2()  asm volatile("cp.async.wait_group 2;" ::: "memory")

// ================= conversions =================
__global__ void __launch_bounds__(256) convW(const float* __restrict__ src,
                                             __half* __restrict__ dh, int K) {
    int row = blockIdx.x, tid = threadIdx.x;
    const float* s = src + (size_t)row * K;
    for (int i = tid * 4; i < K; i += 1024) {
        float4 v = *(const float4*)(s + i);
        *(uint2*)(dh + (size_t)row * K + i) = make_uint2(h2only(v.x, v.y), h2only(v.z, v.w));
    }
}
__global__ void __launch_bounds__(256) convQKV(const float* __restrict__ qw,
                                               const float* __restrict__ kvw) {
    int n = blockIdx.x, tid = threadIdx.x;
    const float* s;
    if (n < 2048) s = qw + (size_t)((n >> 7) * 192 + (n & 127)) * 2048;
    else          s = kvw + (size_t)(n - 2048) * 2048;
    for (int i = tid * 4; i < 2048; i += 1024) {
        float4 v = *(const float4*)(s + i);
        *(uint2*)(c_qkvw + (size_t)n * 2048 + i) = make_uint2(h2only(v.x, v.y), h2only(v.z, v.w));
    }
}
__global__ void __launch_bounds__(256) convPair(const float* __restrict__ src,
                                                __half* __restrict__ dh,
                                                int K, int I) {
    int n = blockIdx.x, tid = threadIdx.x;
    int twoI = 2 * I;
    int e = n / twoI, r = n % twoI;
    int sr = (r & 1) ? (I + (r >> 1)) : (r >> 1);
    const float* s = src + ((size_t)e * twoI + sr) * K;
    for (int i = tid * 4; i < K; i += 1024) {
        float4 v = *(const float4*)(s + i);
        *(uint2*)(dh + (size_t)n * K + i) = make_uint2(h2only(v.x, v.y), h2only(v.z, v.w));
    }
}

// ================= HMMA fp16 GEMM (4-stage ring, occupancy 1) =================
// EPI: 0 = f32 out, 1 = f32 out + addsrc, 2 = fp16 out, 3 = silu(g)*u fp16 out (paired cols)
#define GSMEM_BYTES (4 * 20480)

template <int MODE, int EPI>
__global__ void __launch_bounds__(256, 1) gemm_h(
    const __half* __restrict__ Ahp, long long aestride, int lda,
    const __half* __restrict__ Bhp, long long bestride,
    void* __restrict__ C, long long cstride, int ldc,
    int M, int K,
    const float* __restrict__ addsrc, int ldadd)
{
    extern __shared__ char smem[];
    const int e  = blockIdx.z;
    const int Me = (MODE == 0) ? M : g_cnt[e];
    const int bm = blockIdx.y * 128, bn = blockIdx.x * 128;
    if (bm >= Me) return;
    const __half* AhB = Ahp + (MODE == 2 ? (long long)e * aestride : 0LL);
    const __half* BhB = Bhp + (long long)e * bestride;

    const uint32_t sb = smem_u32(smem);
    const int tid = threadIdx.x, wid = tid >> 5, lid = tid & 31;
    const int wm = wid & 3, wn = wid >> 2;

    uint32_t sOff[2]; uint32_t aval[2];
    const char *aHp[2], *bHp[2];
    #pragma unroll
    for (int i = 0; i < 2; i++) {
        int q = tid + i * 256;
        int row = q >> 2, seg = q & 3;
        sOff[i] = (uint32_t)(row * 80 + seg * 16);
        int gm = bm + row;
        aval[i] = (gm < Me) ? 16u : 0u;
        long long arow;
        if (MODE == 1) arow = (gm < Me) ? (long long)g_tok[e * T_TOK + gm] : 0LL;
        else           arow = (gm < Me) ? (long long)gm : 0LL;
        aHp[i] = (const char*)(AhB + arow * (long long)lda) + seg * 16;
        long long brow = (long long)(bn + row);
        bHp[i] = (const char*)(BhB + brow * (long long)lda) + seg * 16;
    }

    const int laneRow = lid & 15, laneChk = lid >> 4;
    uint32_t aOff[2], bOff[4];
    #pragma unroll
    for (int t = 0; t < 2; t++)
        aOff[t] = (uint32_t)((wm * 32 + t * 16 + laneRow) * 80 + laneChk * 16);
    #pragma unroll
    for (int p = 0; p < 4; p++)
        bOff[p] = (uint32_t)(10240 + (wn * 64 + p * 16 + laneRow) * 80 + laneChk * 16);

    float am[2][8][4];
    #pragma unroll
    for (int t = 0; t < 2; t++)
        #pragma unroll
        for (int n8 = 0; n8 < 8; n8++)
            #pragma unroll
            for (int j = 0; j < 4; j++) am[t][n8][j] = 0.f;

    const int NC = K / 32;

    #define ISSUE(c) do { \
        uint32_t st_ = sb + (uint32_t)((c) & 3) * 20480u; \
        long long kb_ = (long long)(c) * 64; \
        _Pragma("unroll") \
        for (int i_ = 0; i_ < 2; i_++) { \
            CPA16(st_ + sOff[i_],          aHp[i_] + kb_, aval[i_]); \
            CPA16(st_ + 10240u + sOff[i_], bHp[i_] + kb_, 16u); \
        } \
    } while (0)

    ISSUE(0); CPA_COMMIT();
    if (NC > 1) { ISSUE(1); } CPA_COMMIT();
    if (NC > 2) { ISSUE(2); } CPA_COMMIT();

    for (int c = 0; c < NC; c++) {
        CPA_WAIT2();
        __syncthreads();
        const uint32_t stg = sb + (uint32_t)(c & 3) * 20480u;
        #pragma unroll
        for (int h = 0; h < 2; h++) {
            uint32_t ah0[4], ah1[4];
            LDM4(ah0, stg + aOff[0] + h * 32);
            LDM4(ah1, stg + aOff[1] + h * 32);
            #pragma unroll
            for (int p = 0; p < 4; p++) {
                uint32_t bh[4];
                LDM4(bh, stg + bOff[p] + h * 32);
                MMAF32(am[0][2 * p],     ah0, bh[0], bh[2]);
                MMAF32(am[0][2 * p + 1], ah0, bh[1], bh[3]);
                MMAF32(am[1][2 * p],     ah1, bh[0], bh[2]);
                MMAF32(am[1][2 * p + 1], ah1, bh[1], bh[3]);
            }
        }
        __syncthreads();
        if (c + 3 < NC) ISSUE(c + 3);
        CPA_COMMIT();
    }
    #undef ISSUE

    const int g = lid >> 2, tg = lid & 3;
    #pragma unroll
    for (int t = 0; t < 2; t++) {
        #pragma unroll
        for (int half = 0; half < 2; half++) {
            int row = bm + wm * 32 + t * 16 + g + half * 8;
            if (row >= Me) continue;
            #pragma unroll
            for (int n8 = 0; n8 < 8; n8++) {
                float v0 = am[t][n8][half * 2], v1 = am[t][n8][half * 2 + 1];
                if (EPI == 3) {
                    long long idx = (long long)e * cstride + (long long)row * ldc
                                  + (bn >> 1) + wn * 32 + n8 * 4 + tg;
                    ((__half*)C)[idx] = __float2half_rn(silu_f(v0) * v1);
                } else {
                    long long base = (long long)e * cstride + (long long)row * ldc
                                   + bn + wn * 64 + tg * 2 + n8 * 8;
                    if (EPI == 1) {
                        const float* ap = addsrc + (long long)row * ldadd + bn + wn * 64 + tg * 2 + n8 * 8;
                        v0 += ap[0]; v1 += ap[1];
                    }
                    if (EPI == 2) *(uint32_t*)((__half*)C + base) = h2only(v0, v1);
                    else { float* cp = (float*)C + base; cp[0] = v0; cp[1] = v1; }
                }
            }
        }
    }
}

// ---------------- rmsnorm (fp16 plane only) ----------------
__global__ __launch_bounds__(256) void rmsnorm_h(const float* __restrict__ in,
                                                 const float* __restrict__ w,
                                                 __half* __restrict__ ph) {
    __shared__ float red[8];
    int t = blockIdx.x, tid = threadIdx.x;
    const float* row = in + (size_t)t * H_DIM;
    float ss = 0.f;
    for (int i = tid; i < H_DIM; i += 256) { float v = row[i]; ss += v * v; }
    #pragma unroll
    for (int o = 16; o; o >>= 1) ss += __shfl_xor_sync(0xffffffffu, ss, o);
    if ((tid & 31) == 0) red[tid >> 5] = ss;
    __syncthreads();
    float tot = red[0] + red[1] + red[2] + red[3] + red[4] + red[5] + red[6] + red[7];
    float inv = rsqrtf(tot * (1.0f / H_DIM) + 1e-6f);
    for (int i = tid * 2; i < H_DIM; i += 512) {
        float a = row[i] * inv * w[i];
        float b = row[i + 1] * inv * w[i + 1];
        ((uint32_t*)ph)[((size_t)t * H_DIM + i) >> 1] = h2only(a, b);
    }
}

// ---------------- rmsnorm2 + fused gate (routing) ----------------
__global__ __launch_bounds__(256) void rmsnorm_gate(const float* __restrict__ in,
                                                    const float* __restrict__ w,
                                                    __half* __restrict__ ph,
                                                    const float* __restrict__ gate_w) {
    __shared__ float xs[H_DIM];
    __shared__ float red[8];
    __shared__ float lg[E_NUM];
    int t = blockIdx.x, tid = threadIdx.x;
    int wid = tid >> 5, lane = tid & 31;
    const float* row = in + (size_t)t * H_DIM;
    float ss = 0.f;
    for (int i = tid; i < H_DIM; i += 256) { float v = row[i]; xs[i] = v; ss += v * v; }
    #pragma unroll
    for (int o = 16; o; o >>= 1) ss += __shfl_xor_sync(0xffffffffu, ss, o);
    if (lane == 0) red[wid] = ss;
    __syncthreads();
    float tot = red[0] + red[1] + red[2] + red[3] + red[4] + red[5] + red[6] + red[7];
    float inv = rsqrtf(tot * (1.0f / H_DIM) + 1e-6f);
    __syncthreads();
    for (int i = tid * 2; i < H_DIM; i += 512) {
        float a = xs[i] * inv * w[i];
        float b = xs[i + 1] * inv * w[i + 1];
        xs[i] = a; xs[i + 1] = b;
        ((uint32_t*)ph)[((size_t)t * H_DIM + i) >> 1] = h2only(a, b);
    }
    __syncthreads();
    // gate logits: warp wid handles experts wid and wid+8 (lane stride 32 — same order as before)
    #pragma unroll
    for (int eo = 0; eo < 2; eo++) {
        int e = wid + eo * 8;
        const float* gw = gate_w + (size_t)e * H_DIM;
        float s = 0.f;
        for (int i = lane; i < H_DIM; i += 32) s += xs[i] * gw[i];
        #pragma unroll
        for (int o = 16; o; o >>= 1) s += __shfl_xor_sync(0xffffffffu, s, o);
        if (lane == 0) lg[e] = s;
    }
    __syncthreads();
    if (tid == 0) {
        float mx = -1e30f;
        for (int e = 0; e < E_NUM; e++) mx = fmaxf(mx, lg[e]);
        float pe[E_NUM];
        for (int e = 0; e < E_NUM; e++) pe[e] = expf(lg[e] - mx);
        bool used[E_NUM];
        for (int e = 0; e < E_NUM; e++) used[e] = false;
        int sel[4]; float sw[4]; float wsum = 0.f;
        for (int j = 0; j < 4; j++) {
            int bi = -1; float bv = -1.f;
            for (int e = 0; e < E_NUM; e++)
                if (!used[e] && pe[e] > bv) { bv = pe[e]; bi = e; }
            used[bi] = true; sel[j] = bi; sw[j] = bv; wsum += bv;
        }
        for (int j = 0; j < 4; j++) {
            int e = sel[j];
            int pos = atomicAdd(&g_cnt[e], 1);
            g_tok[e * T_TOK + pos] = t;
            g_texp[t * 4 + j] = e;
            g_trow[t * 4 + j] = pos;
            g_twt [t * 4 + j] = sw[j] / wsum;
        }
    }
}

// ---------------- HMMA flash attention (heavy tiles first) ----------------
#define ATTN_SMEM 81920

__global__ void __launch_bounds__(256) attn_mma() {
    extern __shared__ char smem[];
    const uint32_t sb = smem_u32(smem);
    const uint32_t QS = 0, KS = 17408, VT = 34816, PF = 53248;
    float* Ps   = (float*)(smem + 62464);
    float* mrow = (float*)(smem + 79104);
    float* lrow = (float*)(smem + 79360);
    float* corr = (float*)(smem + 79616);
    float* pm4  = (float*)(smem + 79872);
    float* ps4  = (float*)(smem + 80896);
    __half* Vt  = (__half*)(smem + VT);
    __half* Pf  = (__half*)(smem + PF);

    int bh = blockIdx.y; int b = bh >> 4, h = bh & 15;
    int qt = 15 - blockIdx.x;
    int q0 = qt * 64;
    int tb = b * S_LEN;
    int tid = threadIdx.x, wid = tid >> 5, lid = tid & 31;
    int wm = wid & 3, wn = wid >> 2;
    const int laneRow = lid & 15, laneChk = lid >> 4;
    const int g = lid >> 2, tg = lid & 3;
    const float scale = 1.0f / sqrtf(192.0f);

    for (int i = tid; i < 1024; i += 256) {
        int r = i >> 4, c8 = i & 15;
        uint4 v = *(const uint4*)(c_qkvo + (size_t)(tb + q0 + r) * 6144 + h * 128 + c8 * 8);
        *(uint4*)(smem + QS + r * 272 + c8 * 16) = v;
    }
    if (tid < 64) { mrow[tid] = -1e30f; lrow[tid] = 0.f; }

    float acc[8][4];
    #pragma unroll
    for (int n8 = 0; n8 < 8; n8++)
        #pragma unroll
        for (int j = 0; j < 4; j++) acc[n8][j] = 0.f;
    __syncthreads();

    int nkt = qt + 1;
    for (int kt = 0; kt < nkt; kt++) {
        int k0 = kt * 64;
        for (int i = tid; i < 1024; i += 256) {
            int r = i >> 4, c8 = i & 15;
            uint4 v = *(const uint4*)(c_qkvo + (size_t)(tb + k0 + r) * 6144 + 2048 + h * 128 + c8 * 8);
            *(uint4*)(smem + KS + r * 272 + c8 * 16) = v;
        }
        #pragma unroll
        for (int it = 0; it < 4; it++) {
            int u = tid + it * 256;
            int key = (u & 15) | ((u >> 8) << 4);
            int d8 = (u >> 4) & 15;
            uint4 v = *(const uint4*)(c_qkvo + (size_t)(tb + k0 + key) * 6144 + 4096 + h * 128 + d8 * 8);
            __half* hv = (__half*)&v;
            #pragma unroll
            for (int j = 0; j < 8; j++) Vt[(d8 * 8 + j) * 72 + key] = hv[j];
        }
        __syncthreads();

        float sc[4][4];
        #pragma unroll
        for (int f = 0; f < 4; f++)
            #pragma unroll
            for (int j = 0; j < 4; j++) sc[f][j] = 0.f;
        #pragma unroll
        for (int h8 = 0; h8 < 8; h8++) {
            uint32_t aq[4];
            LDM4(aq, sb + QS + (wm * 16 + laneRow) * 272 + h8 * 32 + laneChk * 16);
            #pragma unroll
            for (int p16 = 0; p16 < 2; p16++) {
                uint32_t bk[4];
                LDM4(bk, sb + KS + (wn * 32 + p16 * 16 + laneRow) * 272 + h8 * 32 + laneChk * 16);
                MMAF32(sc[p16 * 2],     aq, bk[0], bk[2]);
                MMAF32(sc[p16 * 2 + 1], aq, bk[1], bk[3]);
            }
        }
        {
            int r0 = wm * 16 + g, r1 = r0 + 8;
            int gr0 = q0 + r0, gr1 = q0 + r1;
            #pragma unroll
            for (int f = 0; f < 4; f++) {
                int cb = wn * 32 + (f >> 1) * 16 + (f & 1) * 8 + tg * 2;
                int ck = k0 + cb;
                Ps[r0 * 65 + cb]     = (ck     <= gr0) ? sc[f][0] * scale : -1e30f;
                Ps[r0 * 65 + cb + 1] = (ck + 1 <= gr0) ? sc[f][1] * scale : -1e30f;
                Ps[r1 * 65 + cb]     = (ck     <= gr1) ? sc[f][2] * scale : -1e30f;
                Ps[r1 * 65 + cb + 1] = (ck + 1 <= gr1) ? sc[f][3] * scale : -1e30f;
            }
        }
        __syncthreads();

        {
            int r = tid & 63, qd = tid >> 6;
            float m0 = mrow[r];
            float pm = -1e30f;
            #pragma unroll 4
            for (int c = qd * 16; c < qd * 16 + 16; c++) pm = fmaxf(pm, Ps[r * 65 + c]);
            pm4[r * 4 + qd] = pm;
            __syncthreads();
            float mx = fmaxf(m0, fmaxf(fmaxf(pm4[r * 4], pm4[r * 4 + 1]),
                                       fmaxf(pm4[r * 4 + 2], pm4[r * 4 + 3])));
            float sum = 0.f;
            #pragma unroll 4
            for (int c = qd * 16; c < qd * 16 + 16; c++) {
                float p = __expf(Ps[r * 65 + c] - mx);
                sum += p;
                Pf[r * 72 + c] = __float2half_rn(p);
            }
            ps4[r * 4 + qd] = sum;
            __syncthreads();
            if (qd == 0) {
                float cr = __expf(m0 - mx);
                corr[r] = cr;
                lrow[r] = lrow[r] * cr + ps4[r * 4] + ps4[r * 4 + 1] + ps4[r * 4 + 2] + ps4[r * 4 + 3];
                mrow[r] = mx;
            }
        }
        __syncthreads();

        {
            float cr0 = corr[wm * 16 + g], cr1 = corr[wm * 16 + g + 8];
            #pragma unroll
            for (int n8 = 0; n8 < 8; n8++) {
                acc[n8][0] *= cr0; acc[n8][1] *= cr0;
                acc[n8][2] *= cr1; acc[n8][3] *= cr1;
            }
        }
        #pragma unroll
        for (int kh = 0; kh < 4; kh++) {
            uint32_t ap[4];
            LDM4(ap, sb + PF + (wm * 16 + laneRow) * 144 + kh * 32 + laneChk * 16);
            #pragma unroll
            for (int p16 = 0; p16 < 4; p16++) {
                uint32_t bv[4];
                LDM4(bv, sb + VT + (wn * 64 + p16 * 16 + laneRow) * 144 + kh * 32 + laneChk * 16);
                MMAF32(acc[p16 * 2],     ap, bv[0], bv[2]);
                MMAF32(acc[p16 * 2 + 1], ap, bv[1], bv[3]);
            }
        }
        __syncthreads();
    }

    {
        int r0 = wm * 16 + g, r1 = r0 + 8;
        float i0 = 1.0f / lrow[r0], i1 = 1.0f / lrow[r1];
        size_t b0 = (size_t)(tb + q0 + r0) * 2048 + h * 128;
        size_t b1 = (size_t)(tb + q0 + r1) * 2048 + h * 128;
        #pragma unroll
        for (int n8 = 0; n8 < 8; n8++) {
            int col = wn * 64 + (n8 >> 1) * 16 + (n8 & 1) * 8 + tg * 2;
            *(uint32_t*)(c_ath + b0 + col) = h2only(acc[n8][0] * i0, acc[n8][1] * i0);
            *(uint32_t*)(c_ath + b1 + col) = h2only(acc[n8][2] * i1, acc[n8][3] * i1);
        }
    }
}

// ---------------- zero counts ----------------
__global__ void __launch_bounds__(32) zero_cnt() { if (threadIdx.x < E_NUM) g_cnt[threadIdx.x] = 0; }

// ---------------- final sum (fp16 down planes) ----------------
__global__ void __launch_bounds__(256) final_sum(float* __restrict__ out) {
    int t = blockIdx.x;
    int e0 = g_texp[t * 4 + 0], e1 = g_texp[t * 4 + 1], e2 = g_texp[t * 4 + 2], e3 = g_texp[t * 4 + 3];
    int r0 = g_trow[t * 4 + 0], r1 = g_trow[t * 4 + 1], r2 = g_trow[t * 4 + 2], r3 = g_trow[t * 4 + 3];
    float w0 = g_twt[t * 4 + 0], w1v = g_twt[t * 4 + 1], w2v = g_twt[t * 4 + 2], w3 = g_twt[t * 4 + 3];
    const __half* d0 = c_down + ((size_t)e0 * T_TOK + r0) * H_DIM;
    const __half* d1 = c_down + ((size_t)e1 * T_TOK + r1) * H_DIM;
    const __half* d2 = c_down + ((size_t)e2 * T_TOK + r2) * H_DIM;
    const __half* d3 = c_down + ((size_t)e3 * T_TOK + r3) * H_DIM;
    for (int h = threadIdx.x * 2; h < H_DIM; h += 512) {
        float2 a0 = __half22float2(*(const __half2*)(d0 + h));
        float2 a1 = __half22float2(*(const __half2*)(d1 + h));
        float2 a2 = __half22float2(*(const __half2*)(d2 + h));
        float2 a3 = __half22float2(*(const __half2*)(d3 + h));
        float* o = out + (size_t)t * H_DIM + h;
        o[0] += w0 * a0.x + w1v * a1.x + w2v * a2.x + w3 * a3.x;
        o[1] += w0 * a0.y + w1v * a1.y + w2v * a2.y + w3 * a3.y;
    }
}

// ---------------- launch ----------------
extern "C" void kernel_launch(void* const* d_in, const int* in_sizes, int n_in,
                              void* d_out, int out_size) {
    (void)in_sizes; (void)n_in; (void)out_size;
    const float* hidden  = (const float*)d_in[0];
    const float* ln1_w   = (const float*)d_in[2];
    const float* ln2_w   = (const float*)d_in[3];
    const float* q_w     = (const float*)d_in[4];
    const float* kv_w    = (const float*)d_in[5];
    const float* o_w     = (const float*)d_in[6];
    const float* gate_w  = (const float*)d_in[7];
    const float* w1      = (const float*)d_in[8];
    const float* w2      = (const float*)d_in[9];
    const float* sh_gu_w = (const float*)d_in[10];
    const float* sh_dn_w = (const float*)d_in[11];
    float* out = (float*)d_out;

    static cudaStream_t s1 = nullptr, s2 = nullptr;
    static cudaEvent_t ev[12];
    if (!s1) {
        cudaStreamCreateWithFlags(&s1, cudaStreamNonBlocking);
        cudaStreamCreateWithFlags(&s2, cudaStreamNonBlocking);
        for (int i = 0; i < 12; i++) cudaEventCreateWithFlags(&ev[i], cudaEventDisableTiming);
    }

    float* pHid;
    cudaGetSymbolAddress((void**)&pHid, g_hid);

    __half *Xh, *qkvo, *ath, *X2h, *guh, *sah, *down;
    __half *qkvw, *owh, *w1h, *w2h, *sgh, *sdh;
    cudaGetSymbolAddress((void**)&Xh, c_Xh);
    cudaGetSymbolAddress((void**)&qkvo, c_qkvo);
    cudaGetSymbolAddress((void**)&ath, c_ath);
    cudaGetSymbolAddress((void**)&X2h, c_X2h);
    cudaGetSymbolAddress((void**)&guh, c_guh);
    cudaGetSymbolAddress((void**)&sah, c_sah);
    cudaGetSymbolAddress((void**)&down, c_down);
    cudaGetSymbolAddress((void**)&qkvw, c_qkvw);
    cudaGetSymbolAddress((void**)&owh, c_owh);
    cudaGetSymbolAddress((void**)&w1h, c_w1h);
    cudaGetSymbolAddress((void**)&w2h, c_w2h);
    cudaGetSymbolAddress((void**)&sgh, c_sgh);
    cudaGetSymbolAddress((void**)&sdh, c_sdh);

    cudaFuncSetAttribute(attn_mma, cudaFuncAttributeMaxDynamicSharedMemorySize, ATTN_SMEM);
    cudaFuncSetAttribute(gemm_h<0, 1>, cudaFuncAttributeMaxDynamicSharedMemorySize, GSMEM_BYTES);
    cudaFuncSetAttribute(gemm_h<0, 2>, cudaFuncAttributeMaxDynamicSharedMemorySize, GSMEM_BYTES);
    cudaFuncSetAttribute(gemm_h<0, 3>, cudaFuncAttributeMaxDynamicSharedMemorySize, GSMEM_BYTES);
    cudaFuncSetAttribute(gemm_h<1, 3>, cudaFuncAttributeMaxDynamicSharedMemorySize, GSMEM_BYTES);
    cudaFuncSetAttribute(gemm_h<2, 2>, cudaFuncAttributeMaxDynamicSharedMemorySize, GSMEM_BYTES);

    // fork side streams
    cudaEventRecord(ev[0], 0);
    cudaStreamWaitEvent(s1, ev[0], 0);
    cudaStreamWaitEvent(s2, ev[0], 0);

    // s2: zero expert counters early (ordered before rmsnorm_gate via ev[2])
    zero_cnt<<<1, 32, 0, s2>>>();
    cudaEventRecord(ev[2], s2);

    // s1: conversions
    convQKV<<<6144, 256, 0, s1>>>(q_w, kv_w);                     cudaEventRecord(ev[1], s1);
    convW<<<2048, 256, 0, s1>>>(o_w, owh, 2048);                  cudaEventRecord(ev[3], s1);
    convPair<<<E_NUM * TWO_I, 256, 0, s1>>>(w1, w1h, 2048, I_DIM);   cudaEventRecord(ev[4], s1);
    convPair<<<SH2, 256, 0, s1>>>(sh_gu_w, sgh, 2048, SHI_DIM);   cudaEventRecord(ev[5], s1);
    convW<<<E_NUM * H_DIM, 256, 0, s1>>>(w2, w2h, 1408);          cudaEventRecord(ev[6], s1);
    convW<<<H_DIM, 256, 0, s1>>>(sh_dn_w, sdh, 2816);             cudaEventRecord(ev[7], s1);

    // s0: rmsnorm -> fp16 X plane
    rmsnorm_h<<<T_TOK, 256>>>(hidden, ln1_w, Xh);

    // s0: merged QKV projection (fp16 out)
    cudaStreamWaitEvent(0, ev[1], 0);
    gemm_h<0, 2><<<dim3(48, 16, 1), 256, GSMEM_BYTES>>>(
        Xh, 0LL, 2048, qkvw, 0LL, qkvo, 0LL, 6144, T_TOK, 2048, nullptr, 0);

    // s0: attention
    attn_mma<<<dim3(16, 32), 256, ATTN_SMEM>>>();

    // s0: hid = attn @ o_w^T + hidden
    cudaStreamWaitEvent(0, ev[3], 0);
    gemm_h<0, 1><<<dim3(16, 16, 1), 256, GSMEM_BYTES>>>(
        ath, 0LL, 2048, owh, 0LL, pHid, 0LL, H_DIM, T_TOK, 2048, hidden, H_DIM);

    // s0: rmsnorm2 + fused gate (needs zero_cnt done)
    cudaStreamWaitEvent(0, ev[2], 0);
    rmsnorm_gate<<<T_TOK, 256>>>(pHid, ln2_w, X2h, gate_w);
    cudaEventRecord(ev[8], 0);  // X2 plane + routing ready

    // s2: routed branch
    cudaStreamWaitEvent(s2, ev[8], 0);
    cudaStreamWaitEvent(s2, ev[4], 0);
    gemm_h<1, 3><<<dim3(22, 16, E_NUM), 256, GSMEM_BYTES, s2>>>(
        X2h, 0LL, 2048, w1h, (long long)TWO_I * H_DIM,
        guh, (long long)T_TOK * I_DIM, I_DIM, 0, 2048, nullptr, 0);
    cudaStreamWaitEvent(s2, ev[6], 0);
    gemm_h<2, 2><<<dim3(16, 16, E_NUM), 256, GSMEM_BYTES, s2>>>(
        guh, (long long)T_TOK * I_DIM, 1408, w2h, (long long)H_DIM * I_DIM,
        down, (long long)T_TOK * H_DIM, H_DIM, 0, 1408, nullptr, 0);
    cudaEventRecord(ev[9], s2);

    // s0: shared branch
    cudaStreamWaitEvent(0, ev[5], 0);
    gemm_h<0, 3><<<dim3(44, 16, 1), 256, GSMEM_BYTES>>>(
        X2h, 0LL, 2048, sgh, 0LL, sah, 0LL, SHI_DIM, T_TOK, 2048, nullptr, 0);
    cudaStreamWaitEvent(0, ev[7], 0);
    gemm_h<0, 1><<<dim3(16, 16, 1), 256, GSMEM_BYTES>>>(
        sah, 0LL, 2816, sdh, 0LL, out, 0LL, H_DIM, T_TOK, 2816, pHid, H_DIM);

    // join routed, final combine
    cudaStreamWaitEvent(0, ev[9], 0);
    final_sum<<<T_TOK, 256>>>(out);
}

// round 15
// speedup vs baseline: 1.4251x; 1.4251x over previous
#include <cuda_runtime.h>
#include <cuda_fp16.h>
#include <cstdint>
#include <math.h>

#define T_TOK 2048
#define H_DIM 2048
#define S_LEN 1024
#define E_NUM 16
#define I_DIM 1408
#define TWO_I 2816
#define SHI_DIM 2816
#define SH2 5632

// ---------------- fp32 scratch ----------------
__device__ float g_hid [(size_t)T_TOK * H_DIM];
__device__ float g_X2  [(size_t)T_TOK * H_DIM];
__device__ int   g_cnt [E_NUM];
__device__ int   g_tok [E_NUM * T_TOK];
__device__ int   g_texp[T_TOK * 4];
__device__ int   g_trow[T_TOK * 4];
__device__ float g_twt [T_TOK * 4];

// ---------------- fp16 planes ----------------
__device__ __half c_Xh  [(size_t)T_TOK * H_DIM];
__device__ __half c_qkvo[(size_t)T_TOK * 6144];
__device__ __half c_ath [(size_t)T_TOK * 2048];
__device__ __half c_X2h [(size_t)T_TOK * H_DIM];
__device__ __half c_guh [(size_t)E_NUM * T_TOK * I_DIM];
__device__ __half c_sah [(size_t)T_TOK * SHI_DIM];
__device__ __half c_down[(size_t)E_NUM * T_TOK * H_DIM];
__device__ __half c_qkvw[(size_t)6144 * 2048];
__device__ __half c_owh [(size_t)2048 * 2048];
__device__ __half c_w1h [(size_t)E_NUM * TWO_I * H_DIM];
__device__ __half c_w2h [(size_t)E_NUM * H_DIM * I_DIM];
__device__ __half c_sgh [(size_t)SH2 * H_DIM];
__device__ __half c_sdh [(size_t)H_DIM * SHI_DIM];

// ================= helpers =================
static __device__ __forceinline__ uint32_t smem_u32(const void* p) {
    uint32_t a;
    asm("{ .reg .u64 t; cvta.to.shared.u64 t, %1; cvt.u32.u64 %0, t; }" : "=r"(a) : "l"(p));
    return a;
}
static __device__ __forceinline__ uint32_t h2only(float x, float y) {
    __half2 hp = __halves2half2(__float2half_rn(x), __float2half_rn(y));
    return *(uint32_t*)&hp;
}
__device__ __forceinline__ float silu_f(float x) { return x / (1.0f + __expf(-x)); }
#define LDM4(r, a) \
    asm volatile("ldmatrix.sync.aligned.m8n8.x4.shared.b16 {%0,%1,%2,%3}, [%4];" \
        : "=r"((r)[0]), "=r"((r)[1]), "=r"((r)[2]), "=r"((r)[3]) : "r"(a))
#define MMAF32(c, a, b0, b1) \
    asm volatile("mma.sync.aligned.m16n8k16.row.col.f32.f16.f16.f32 " \
        "{%0,%1,%2,%3}, {%4,%5,%6,%7}, {%8,%9}, {%0,%1,%2,%3};" \
        : "+f"((c)[0]), "+f"((c)[1]), "+f"((c)[2]), "+f"((c)[3]) \
        : "r"((a)[0]), "r"((a)[1]), "r"((a)[2]), "r"((a)[3]), "r"(b0), "r"(b1))
#define CPA16(d, s, n) \
    asm volatile("cp.async.cg.shared.global [%0], [%1], 16, %2;" :: "r"(d), "l"(s), "r"(n) : "memory")
#define CPA_COMMIT() asm volatile("cp.async.commit_group;" ::: "memory")
#define CPA_WAIT2()  asm volatile("cp.async.wait_group 2;" ::: "memory")

// ================= conversions =================
__global__ void __launch_bounds__(256) convW(const float* __restrict__ src,
                                             __half* __restrict__ dh, int K) {
    int row = blockIdx.x, tid = threadIdx.x;
    const float* s = src + (size_t)row * K;
    for (int i = tid * 4; i < K; i += 1024) {
        float4 v = *(const float4*)(s + i);
        *(uint2*)(dh + (size_t)row * K + i) = make_uint2(h2only(v.x, v.y), h2only(v.z, v.w));
    }
}
__global__ void __launch_bounds__(256) convQKV(const float* __restrict__ qw,
                                               const float* __restrict__ kvw) {
    int n = blockIdx.x, tid = threadIdx.x;
    const float* s;
    if (n < 2048) s = qw + (size_t)((n >> 7) * 192 + (n & 127)) * 2048;
    else          s = kvw + (size_t)(n - 2048) * 2048;
    for (int i = tid * 4; i < 2048; i += 1024) {
        float4 v = *(const float4*)(s + i);
        *(uint2*)(c_qkvw + (size_t)n * 2048 + i) = make_uint2(h2only(v.x, v.y), h2only(v.z, v.w));
    }
}
__global__ void __launch_bounds__(256) convPair(const float* __restrict__ src,
                                                __half* __restrict__ dh,
                                                int K, int I) {
    int n = blockIdx.x, tid = threadIdx.x;
    int twoI = 2 * I;
    int e = n / twoI, r = n % twoI;
    int sr = (r & 1) ? (I + (r >> 1)) : (r >> 1);
    const float* s = src + ((size_t)e * twoI + sr) * K;
    for (int i = tid * 4; i < K; i += 1024) {
        float4 v = *(const float4*)(s + i);
        *(uint2*)(dh + (size_t)n * K + i) = make_uint2(h2only(v.x, v.y), h2only(v.z, v.w));
    }
}

// ================= HMMA fp16 GEMM (4-stage ring, occupancy 1) =================
// EPI: 0 = f32 out, 1 = f32 out + addsrc, 2 = fp16 out, 3 = silu(g)*u fp16 out (paired cols)
#define GSMEM_BYTES (4 * 20480)

template <int MODE, int EPI>
__global__ void __launch_bounds__(256, 1) gemm_h(
    const __half* __restrict__ Ahp, long long aestride, int lda,
    const __half* __restrict__ Bhp, long long bestride,
    void* __restrict__ C, long long cstride, int ldc,
    int M, int K,
    const float* __restrict__ addsrc, int ldadd)
{
    extern __shared__ char smem[];
    const int e  = blockIdx.z;
    const int Me = (MODE == 0) ? M : g_cnt[e];
    const int bm = blockIdx.y * 128, bn = blockIdx.x * 128;
    if (bm >= Me) return;
    const __half* AhB = Ahp + (MODE == 2 ? (long long)e * aestride : 0LL);
    const __half* BhB = Bhp + (long long)e * bestride;

    const uint32_t sb = smem_u32(smem);
    const int tid = threadIdx.x, wid = tid >> 5, lid = tid & 31;
    const int wm = wid & 3, wn = wid >> 2;

    uint32_t sOff[2]; uint32_t aval[2];
    const char *aHp[2], *bHp[2];
    #pragma unroll
    for (int i = 0; i < 2; i++) {
        int q = tid + i * 256;
        int row = q >> 2, seg = q & 3;
        sOff[i] = (uint32_t)(row * 80 + seg * 16);
        int gm = bm + row;
        aval[i] = (gm < Me) ? 16u : 0u;
        long long arow;
        if (MODE == 1) arow = (gm < Me) ? (long long)g_tok[e * T_TOK + gm] : 0LL;
        else           arow = (gm < Me) ? (long long)gm : 0LL;
        aHp[i] = (const char*)(AhB + arow * (long long)lda) + seg * 16;
        long long brow = (long long)(bn + row);
        bHp[i] = (const char*)(BhB + brow * (long long)lda) + seg * 16;
    }

    const int laneRow = lid & 15, laneChk = lid >> 4;
    uint32_t aOff[2], bOff[4];
    #pragma unroll
    for (int t = 0; t < 2; t++)
        aOff[t] = (uint32_t)((wm * 32 + t * 16 + laneRow) * 80 + laneChk * 16);
    #pragma unroll
    for (int p = 0; p < 4; p++)
        bOff[p] = (uint32_t)(10240 + (wn * 64 + p * 16 + laneRow) * 80 + laneChk * 16);

    float am[2][8][4];
    #pragma unroll
    for (int t = 0; t < 2; t++)
        #pragma unroll
        for (int n8 = 0; n8 < 8; n8++)
            #pragma unroll
            for (int j = 0; j < 4; j++) am[t][n8][j] = 0.f;

    const int NC = K / 32;

    #define ISSUE(c) do { \
        uint32_t st_ = sb + (uint32_t)((c) & 3) * 20480u; \
        long long kb_ = (long long)(c) * 64; \
        _Pragma("unroll") \
        for (int i_ = 0; i_ < 2; i_++) { \
            CPA16(st_ + sOff[i_],          aHp[i_] + kb_, aval[i_]); \
            CPA16(st_ + 10240u + sOff[i_], bHp[i_] + kb_, 16u); \
        } \
    } while (0)

    ISSUE(0); CPA_COMMIT();
    if (NC > 1) { ISSUE(1); } CPA_COMMIT();
    if (NC > 2) { ISSUE(2); } CPA_COMMIT();

    for (int c = 0; c < NC; c++) {
        CPA_WAIT2();
        __syncthreads();
        const uint32_t stg = sb + (uint32_t)(c & 3) * 20480u;
        #pragma unroll
        for (int h = 0; h < 2; h++) {
            uint32_t ah0[4], ah1[4];
            LDM4(ah0, stg + aOff[0] + h * 32);
            LDM4(ah1, stg + aOff[1] + h * 32);
            #pragma unroll
            for (int p = 0; p < 4; p++) {
                uint32_t bh[4];
                LDM4(bh, stg + bOff[p] + h * 32);
                MMAF32(am[0][2 * p],     ah0, bh[0], bh[2]);
                MMAF32(am[0][2 * p + 1], ah0, bh[1], bh[3]);
                MMAF32(am[1][2 * p],     ah1, bh[0], bh[2]);
                MMAF32(am[1][2 * p + 1], ah1, bh[1], bh[3]);
            }
        }
        __syncthreads();
        if (c + 3 < NC) ISSUE(c + 3);
        CPA_COMMIT();
    }
    #undef ISSUE

    const int g = lid >> 2, tg = lid & 3;
    #pragma unroll
    for (int t = 0; t < 2; t++) {
        #pragma unroll
        for (int half = 0; half < 2; half++) {
            int row = bm + wm * 32 + t * 16 + g + half * 8;
            if (row >= Me) continue;
            #pragma unroll
            for (int n8 = 0; n8 < 8; n8++) {
                float v0 = am[t][n8][half * 2], v1 = am[t][n8][half * 2 + 1];
                if (EPI == 3) {
                    long long idx = (long long)e * cstride + (long long)row * ldc
                                  + (bn >> 1) + wn * 32 + n8 * 4 + tg;
                    ((__half*)C)[idx] = __float2half_rn(silu_f(v0) * v1);
                } else {
                    long long base = (long long)e * cstride + (long long)row * ldc
                                   + bn + wn * 64 + tg * 2 + n8 * 8;
                    if (EPI == 1) {
                        const float* ap = addsrc + (long long)row * ldadd + bn + wn * 64 + tg * 2 + n8 * 8;
                        v0 += ap[0]; v1 += ap[1];
                    }
                    if (EPI == 2) *(uint32_t*)((__half*)C + base) = h2only(v0, v1);
                    else { float* cp = (float*)C + base; cp[0] = v0; cp[1] = v1; }
                }
            }
        }
    }
}

// ---------------- rmsnorm (optional fp32 out + fp16 plane) ----------------
__global__ __launch_bounds__(256) void rmsnorm_h(const float* __restrict__ in,
                                                 const float* __restrict__ w,
                                                 float* __restrict__ out,
                                                 __half* __restrict__ ph) {
    __shared__ float red[8];
    int t = blockIdx.x, tid = threadIdx.x;
    const float* row = in + (size_t)t * H_DIM;
    float ss = 0.f;
    for (int i = tid; i < H_DIM; i += 256) { float v = row[i]; ss += v * v; }
    #pragma unroll
    for (int o = 16; o; o >>= 1) ss += __shfl_xor_sync(0xffffffffu, ss, o);
    if ((tid & 31) == 0) red[tid >> 5] = ss;
    __syncthreads();
    float tot = red[0] + red[1] + red[2] + red[3] + red[4] + red[5] + red[6] + red[7];
    float inv = rsqrtf(tot * (1.0f / H_DIM) + 1e-6f);
    for (int i = tid * 2; i < H_DIM; i += 512) {
        float a = row[i] * inv * w[i];
        float b = row[i + 1] * inv * w[i + 1];
        if (out) { out[(size_t)t * H_DIM + i] = a; out[(size_t)t * H_DIM + i + 1] = b; }
        ((uint32_t*)ph)[((size_t)t * H_DIM + i) >> 1] = h2only(a, b);
    }
}

// ---------------- HMMA flash attention (heavy tiles first) ----------------
#define ATTN_SMEM 81920

__global__ void __launch_bounds__(256) attn_mma() {
    extern __shared__ char smem[];
    const uint32_t sb = smem_u32(smem);
    const uint32_t QS = 0, KS = 17408, VT = 34816, PF = 53248;
    float* Ps   = (float*)(smem + 62464);
    float* mrow = (float*)(smem + 79104);
    float* lrow = (float*)(smem + 79360);
    float* corr = (float*)(smem + 79616);
    float* pm4  = (float*)(smem + 79872);
    float* ps4  = (float*)(smem + 80896);
    __half* Vt  = (__half*)(smem + VT);
    __half* Pf  = (__half*)(smem + PF);

    int bh = blockIdx.y; int b = bh >> 4, h = bh & 15;
    int qt = 15 - blockIdx.x;
    int q0 = qt * 64;
    int tb = b * S_LEN;
    int tid = threadIdx.x, wid = tid >> 5, lid = tid & 31;
    int wm = wid & 3, wn = wid >> 2;
    const int laneRow = lid & 15, laneChk = lid >> 4;
    const int g = lid >> 2, tg = lid & 3;
    const float scale = 1.0f / sqrtf(192.0f);

    for (int i = tid; i < 1024; i += 256) {
        int r = i >> 4, c8 = i & 15;
        uint4 v = *(const uint4*)(c_qkvo + (size_t)(tb + q0 + r) * 6144 + h * 128 + c8 * 8);
        *(uint4*)(smem + QS + r * 272 + c8 * 16) = v;
    }
    if (tid < 64) { mrow[tid] = -1e30f; lrow[tid] = 0.f; }

    float acc[8][4];
    #pragma unroll
    for (int n8 = 0; n8 < 8; n8++)
        #pragma unroll
        for (int j = 0; j < 4; j++) acc[n8][j] = 0.f;
    __syncthreads();

    int nkt = qt + 1;
    for (int kt = 0; kt < nkt; kt++) {
        int k0 = kt * 64;
        for (int i = tid; i < 1024; i += 256) {
            int r = i >> 4, c8 = i & 15;
            uint4 v = *(const uint4*)(c_qkvo + (size_t)(tb + k0 + r) * 6144 + 2048 + h * 128 + c8 * 8);
            *(uint4*)(smem + KS + r * 272 + c8 * 16) = v;
        }
        #pragma unroll
        for (int it = 0; it < 4; it++) {
            int u = tid + it * 256;
            int key = (u & 15) | ((u >> 8) << 4);
            int d8 = (u >> 4) & 15;
            uint4 v = *(const uint4*)(c_qkvo + (size_t)(tb + k0 + key) * 6144 + 4096 + h * 128 + d8 * 8);
            __half* hv = (__half*)&v;
            #pragma unroll
            for (int j = 0; j < 8; j++) Vt[(d8 * 8 + j) * 72 + key] = hv[j];
        }
        __syncthreads();

        float sc[4][4];
        #pragma unroll
        for (int f = 0; f < 4; f++)
            #pragma unroll
            for (int j = 0; j < 4; j++) sc[f][j] = 0.f;
        #pragma unroll
        for (int h8 = 0; h8 < 8; h8++) {
            uint32_t aq[4];
            LDM4(aq, sb + QS + (wm * 16 + laneRow) * 272 + h8 * 32 + laneChk * 16);
            #pragma unroll
            for (int p16 = 0; p16 < 2; p16++) {
                uint32_t bk[4];
                LDM4(bk, sb + KS + (wn * 32 + p16 * 16 + laneRow) * 272 + h8 * 32 + laneChk * 16);
                MMAF32(sc[p16 * 2],     aq, bk[0], bk[2]);
                MMAF32(sc[p16 * 2 + 1], aq, bk[1], bk[3]);
            }
        }
        {
            int r0 = wm * 16 + g, r1 = r0 + 8;
            int gr0 = q0 + r0, gr1 = q0 + r1;
            #pragma unroll
            for (int f = 0; f < 4; f++) {
                int cb = wn * 32 + (f >> 1) * 16 + (f & 1) * 8 + tg * 2;
                int ck = k0 + cb;
                Ps[r0 * 65 + cb]     = (ck     <= gr0) ? sc[f][0] * scale : -1e30f;
                Ps[r0 * 65 + cb + 1] = (ck + 1 <= gr0) ? sc[f][1] * scale : -1e30f;
                Ps[r1 * 65 + cb]     = (ck     <= gr1) ? sc[f][2] * scale : -1e30f;
                Ps[r1 * 65 + cb + 1] = (ck + 1 <= gr1) ? sc[f][3] * scale : -1e30f;
            }
        }
        __syncthreads();

        {
            int r = tid & 63, qd = tid >> 6;
            float m0 = mrow[r];
            float pm = -1e30f;
            #pragma unroll 4
            for (int c = qd * 16; c < qd * 16 + 16; c++) pm = fmaxf(pm, Ps[r * 65 + c]);
            pm4[r * 4 + qd] = pm;
            __syncthreads();
            float mx = fmaxf(m0, fmaxf(fmaxf(pm4[r * 4], pm4[r * 4 + 1]),
                                       fmaxf(pm4[r * 4 + 2], pm4[r * 4 + 3])));
            float sum = 0.f;
            #pragma unroll 4
            for (int c = qd * 16; c < qd * 16 + 16; c++) {
                float p = __expf(Ps[r * 65 + c] - mx);
                sum += p;
                Pf[r * 72 + c] = __float2half_rn(p);
            }
            ps4[r * 4 + qd] = sum;
            __syncthreads();
            if (qd == 0) {
                float cr = __expf(m0 - mx);
                corr[r] = cr;
                lrow[r] = lrow[r] * cr + ps4[r * 4] + ps4[r * 4 + 1] + ps4[r * 4 + 2] + ps4[r * 4 + 3];
                mrow[r] = mx;
            }
        }
        __syncthreads();

        {
            float cr0 = corr[wm * 16 + g], cr1 = corr[wm * 16 + g + 8];
            #pragma unroll
            for (int n8 = 0; n8 < 8; n8++) {
                acc[n8][0] *= cr0; acc[n8][1] *= cr0;
                acc[n8][2] *= cr1; acc[n8][3] *= cr1;
            }
        }
        #pragma unroll
        for (int kh = 0; kh < 4; kh++) {
            uint32_t ap[4];
            LDM4(ap, sb + PF + (wm * 16 + laneRow) * 144 + kh * 32 + laneChk * 16);
            #pragma unroll
            for (int p16 = 0; p16 < 4; p16++) {
                uint32_t bv[4];
                LDM4(bv, sb + VT + (wn * 64 + p16 * 16 + laneRow) * 144 + kh * 32 + laneChk * 16);
                MMAF32(acc[p16 * 2],     ap, bv[0], bv[2]);
                MMAF32(acc[p16 * 2 + 1], ap, bv[1], bv[3]);
            }
        }
        __syncthreads();
    }

    {
        int r0 = wm * 16 + g, r1 = r0 + 8;
        float i0 = 1.0f / lrow[r0], i1 = 1.0f / lrow[r1];
        size_t b0 = (size_t)(tb + q0 + r0) * 2048 + h * 128;
        size_t b1 = (size_t)(tb + q0 + r1) * 2048 + h * 128;
        #pragma unroll
        for (int n8 = 0; n8 < 8; n8++) {
            int col = wn * 64 + (n8 >> 1) * 16 + (n8 & 1) * 8 + tg * 2;
            *(uint32_t*)(c_ath + b0 + col) = h2only(acc[n8][0] * i0, acc[n8][1] * i0);
            *(uint32_t*)(c_ath + b1 + col) = h2only(acc[n8][2] * i1, acc[n8][3] * i1);
        }
    }
}

// ---------------- gate ----------------
__global__ void __launch_bounds__(512) zero_cnt() { if (threadIdx.x < E_NUM) g_cnt[threadIdx.x] = 0; }

__global__ void __launch_bounds__(512) gate_kernel(const float* __restrict__ gate_w) {
    int t = blockIdx.x;
    int w = threadIdx.x >> 5, lane = threadIdx.x & 31;
    const float* x = g_X2 + (size_t)t * H_DIM;
    const float* gw = gate_w + (size_t)w * H_DIM;
    float s = 0.f;
    for (int i = lane; i < H_DIM; i += 32) s += x[i] * gw[i];
    #pragma unroll
    for (int o = 16; o; o >>= 1) s += __shfl_xor_sync(0xffffffffu, s, o);
    __shared__ float lg[E_NUM];
    if (lane == 0) lg[w] = s;
    __syncthreads();
    if (threadIdx.x == 0) {
        float mx = -1e30f;
        for (int e = 0; e < E_NUM; e++) mx = fmaxf(mx, lg[e]);
        float pe[E_NUM];
        for (int e = 0; e < E_NUM; e++) pe[e] = expf(lg[e] - mx);
        bool used[E_NUM];
        for (int e = 0; e < E_NUM; e++) used[e] = false;
        int sel[4]; float sw[4]; float wsum = 0.f;
        for (int j = 0; j < 4; j++) {
            int bi = -1; float bv = -1.f;
            for (int e = 0; e < E_NUM; e++)
                if (!used[e] && pe[e] > bv) { bv = pe[e]; bi = e; }
            used[bi] = true; sel[j] = bi; sw[j] = bv; wsum += bv;
        }
        for (int j = 0; j < 4; j++) {
            int e = sel[j];
            int pos = atomicAdd(&g_cnt[e], 1);
            g_tok[e * T_TOK + pos] = t;
            g_texp[t * 4 + j] = e;
            g_trow[t * 4 + j] = pos;
            g_twt [t * 4 + j] = sw[j] / wsum;
        }
    }
}

// ---------------- final sum (fp16 down planes) ----------------
__global__ void __launch_bounds__(256) final_sum(float* __restrict__ out) {
    int t = blockIdx.x;
    int e0 = g_texp[t * 4 + 0], e1 = g_texp[t * 4 + 1], e2 = g_texp[t * 4 + 2], e3 = g_texp[t * 4 + 3];
    int r0 = g_trow[t * 4 + 0], r1 = g_trow[t * 4 + 1], r2 = g_trow[t * 4 + 2], r3 = g_trow[t * 4 + 3];
    float w0 = g_twt[t * 4 + 0], w1v = g_twt[t * 4 + 1], w2v = g_twt[t * 4 + 2], w3 = g_twt[t * 4 + 3];
    const __half* d0 = c_down + ((size_t)e0 * T_TOK + r0) * H_DIM;
    const __half* d1 = c_down + ((size_t)e1 * T_TOK + r1) * H_DIM;
    const __half* d2 = c_down + ((size_t)e2 * T_TOK + r2) * H_DIM;
    const __half* d3 = c_down + ((size_t)e3 * T_TOK + r3) * H_DIM;
    for (int h = threadIdx.x * 2; h < H_DIM; h += 512) {
        float2 a0 = __half22float2(*(const __half2*)(d0 + h));
        float2 a1 = __half22float2(*(const __half2*)(d1 + h));
        float2 a2 = __half22float2(*(const __half2*)(d2 + h));
        float2 a3 = __half22float2(*(const __half2*)(d3 + h));
        float* o = out + (size_t)t * H_DIM + h;
        o[0] += w0 * a0.x + w1v * a1.x + w2v * a2.x + w3 * a3.x;
        o[1] += w0 * a0.y + w1v * a1.y + w2v * a2.y + w3 * a3.y;
    }
}

// ---------------- launch ----------------
extern "C" void kernel_launch(void* const* d_in, const int* in_sizes, int n_in,
                              void* d_out, int out_size) {
    (void)in_sizes; (void)n_in; (void)out_size;
    const float* hidden  = (const float*)d_in[0];
    const float* ln1_w   = (const float*)d_in[2];
    const float* ln2_w   = (const float*)d_in[3];
    const float* q_w     = (const float*)d_in[4];
    const float* kv_w    = (const float*)d_in[5];
    const float* o_w     = (const float*)d_in[6];
    const float* gate_w  = (const float*)d_in[7];
    const float* w1      = (const float*)d_in[8];
    const float* w2      = (const float*)d_in[9];
    const float* sh_gu_w = (const float*)d_in[10];
    const float* sh_dn_w = (const float*)d_in[11];
    float* out = (float*)d_out;

    static cudaStream_t s1 = nullptr, s2 = nullptr;
    static cudaEvent_t ev[12];
    if (!s1) {
        cudaStreamCreateWithFlags(&s1, cudaStreamNonBlocking);
        cudaStreamCreateWithFlags(&s2, cudaStreamNonBlocking);
        for (int i = 0; i < 12; i++) cudaEventCreateWithFlags(&ev[i], cudaEventDisableTiming);
    }

    float *pHid, *pX2;
    cudaGetSymbolAddress((void**)&pHid, g_hid);
    cudaGetSymbolAddress((void**)&pX2, g_X2);

    __half *Xh, *qkvo, *ath, *X2h, *guh, *sah, *down;
    __half *qkvw, *owh, *w1h, *w2h, *sgh, *sdh;
    cudaGetSymbolAddress((void**)&Xh, c_Xh);
    cudaGetSymbolAddress((void**)&qkvo, c_qkvo);
    cudaGetSymbolAddress((void**)&ath, c_ath);
    cudaGetSymbolAddress((void**)&X2h, c_X2h);
    cudaGetSymbolAddress((void**)&guh, c_guh);
    cudaGetSymbolAddress((void**)&sah, c_sah);
    cudaGetSymbolAddress((void**)&down, c_down);
    cudaGetSymbolAddress((void**)&qkvw, c_qkvw);
    cudaGetSymbolAddress((void**)&owh, c_owh);
    cudaGetSymbolAddress((void**)&w1h, c_w1h);
    cudaGetSymbolAddress((void**)&w2h, c_w2h);
    cudaGetSymbolAddress((void**)&sgh, c_sgh);
    cudaGetSymbolAddress((void**)&sdh, c_sdh);

    cudaFuncSetAttribute(attn_mma, cudaFuncAttributeMaxDynamicSharedMemorySize, ATTN_SMEM);
    cudaFuncSetAttribute(gemm_h<0, 1>, cudaFuncAttributeMaxDynamicSharedMemorySize, GSMEM_BYTES);
    cudaFuncSetAttribute(gemm_h<0, 2>, cudaFuncAttributeMaxDynamicSharedMemorySize, GSMEM_BYTES);
    cudaFuncSetAttribute(gemm_h<0, 3>, cudaFuncAttributeMaxDynamicSharedMemorySize, GSMEM_BYTES);
    cudaFuncSetAttribute(gemm_h<1, 3>, cudaFuncAttributeMaxDynamicSharedMemorySize, GSMEM_BYTES);
    cudaFuncSetAttribute(gemm_h<2, 2>, cudaFuncAttributeMaxDynamicSharedMemorySize, GSMEM_BYTES);

    // fork side streams
    cudaEventRecord(ev[0], 0);
    cudaStreamWaitEvent(s1, ev[0], 0);
    cudaStreamWaitEvent(s2, ev[0], 0);

    // s1: conversions
    convQKV<<<6144, 256, 0, s1>>>(q_w, kv_w);                     cudaEventRecord(ev[1], s1);
    convW<<<2048, 256, 0, s1>>>(o_w, owh, 2048);                  cudaEventRecord(ev[3], s1);
    convPair<<<E_NUM * TWO_I, 256, 0, s1>>>(w1, w1h, 2048, I_DIM);   cudaEventRecord(ev[4], s1);
    convPair<<<SH2, 256, 0, s1>>>(sh_gu_w, sgh, 2048, SHI_DIM);   cudaEventRecord(ev[5], s1);
    convW<<<E_NUM * H_DIM, 256, 0, s1>>>(w2, w2h, 1408);          cudaEventRecord(ev[6], s1);
    convW<<<H_DIM, 256, 0, s1>>>(sh_dn_w, sdh, 2816);             cudaEventRecord(ev[7], s1);

    // s0: rmsnorm -> fp16 X plane
    rmsnorm_h<<<T_TOK, 256>>>(hidden, ln1_w, nullptr, Xh);

    // s0: merged QKV projection (fp16 out)
    cudaStreamWaitEvent(0, ev[1], 0);
    gemm_h<0, 2><<<dim3(48, 16, 1), 256, GSMEM_BYTES>>>(
        Xh, 0LL, 2048, qkvw, 0LL, qkvo, 0LL, 6144, T_TOK, 2048, nullptr, 0);

    // s0: attention
    attn_mma<<<dim3(16, 32), 256, ATTN_SMEM>>>();

    // s0: hid = attn @ o_w^T + hidden
    cudaStreamWaitEvent(0, ev[3], 0);
    gemm_h<0, 1><<<dim3(16, 16, 1), 256, GSMEM_BYTES>>>(
        ath, 0LL, 2048, owh, 0LL, pHid, 0LL, H_DIM, T_TOK, 2048, hidden, H_DIM);
    rmsnorm_h<<<T_TOK, 256>>>(pHid, ln2_w, pX2, X2h);
    cudaEventRecord(ev[8], 0);

    // s2: routed branch
    cudaStreamWaitEvent(s2, ev[8], 0);
    zero_cnt<<<1, 32, 0, s2>>>();
    gate_kernel<<<T_TOK, 512, 0, s2>>>(gate_w);
    cudaStreamWaitEvent(s2, ev[4], 0);
    gemm_h<1, 3><<<dim3(22, 16, E_NUM), 256, GSMEM_BYTES, s2>>>(
        X2h, 0LL, 2048, w1h, (long long)TWO_I * H_DIM,
        guh, (long long)T_TOK * I_DIM, I_DIM, 0, 2048, nullptr, 0);
    cudaStreamWaitEvent(s2, ev[6], 0);
    gemm_h<2, 2><<<dim3(16, 16, E_NUM), 256, GSMEM_BYTES, s2>>>(
        guh, (long long)T_TOK * I_DIM, 1408, w2h, (long long)H_DIM * I_DIM,
        down, (long long)T_TOK * H_DIM, H_DIM, 0, 1408, nullptr, 0);
    cudaEventRecord(ev[9], s2);

    // s0: shared branch
    cudaStreamWaitEvent(0, ev[5], 0);
    gemm_h<0, 3><<<dim3(44, 16, 1), 256, GSMEM_BYTES>>>(
        X2h, 0LL, 2048, sgh, 0LL, sah, 0LL, SHI_DIM, T_TOK, 2048, nullptr, 0);
    cudaStreamWaitEvent(0, ev[7], 0);
    gemm_h<0, 1><<<dim3(16, 16, 1), 256, GSMEM_BYTES>>>(
        sah, 0LL, 2816, sdh, 0LL, out, 0LL, H_DIM, T_TOK, 2816, pHid, H_DIM);

    // join routed, final combine
    cudaStreamWaitEvent(0, ev[9], 0);
    final_sum<<<T_TOK, 256>>>(out);
}

// round 16
// speedup vs baseline: 1.4665x; 1.0291x over previous
#include <cuda_runtime.h>
#include <cuda_fp16.h>
#include <cstdint>
#include <math.h>

#define T_TOK 2048
#define H_DIM 2048
#define S_LEN 1024
#define E_NUM 16
#define I_DIM 1408
#define TWO_I 2816
#define SHI_DIM 2816
#define SH2 5632

// ---------------- fp32 scratch ----------------
__device__ float g_hid [(size_t)T_TOK * H_DIM];
__device__ float g_X2  [(size_t)T_TOK * H_DIM];
__device__ int   g_cnt [E_NUM];
__device__ int   g_tok [E_NUM * T_TOK];
__device__ int   g_texp[T_TOK * 4];
__device__ int   g_trow[T_TOK * 4];
__device__ float g_twt [T_TOK * 4];

// ---------------- fp16 planes ----------------
__device__ __half c_Xh  [(size_t)T_TOK * H_DIM];
__device__ __half c_qkvo[(size_t)T_TOK * 6144];
__device__ __half c_ath [(size_t)T_TOK * 2048];
__device__ __half c_X2h [(size_t)T_TOK * H_DIM];
__device__ __half c_guh [(size_t)E_NUM * T_TOK * I_DIM];
__device__ __half c_sah [(size_t)T_TOK * SHI_DIM];
__device__ __half c_down[(size_t)E_NUM * T_TOK * H_DIM];
__device__ __half c_qkvw[(size_t)6144 * 2048];
__device__ __half c_owh [(size_t)2048 * 2048];
__device__ __half c_w1h [(size_t)E_NUM * TWO_I * H_DIM];
__device__ __half c_w2h [(size_t)E_NUM * H_DIM * I_DIM];
__device__ __half c_sgh [(size_t)SH2 * H_DIM];
__device__ __half c_sdh [(size_t)H_DIM * SHI_DIM];

// ================= helpers =================
static __device__ __forceinline__ uint32_t smem_u32(const void* p) {
    uint32_t a;
    asm("{ .reg .u64 t; cvta.to.shared.u64 t, %1; cvt.u32.u64 %0, t; }" : "=r"(a) : "l"(p));
    return a;
}
static __device__ __forceinline__ uint32_t h2only(float x, float y) {
    __half2 hp = __halves2half2(__float2half_rn(x), __float2half_rn(y));
    return *(uint32_t*)&hp;
}
__device__ __forceinline__ float silu_f(float x) { return x / (1.0f + __expf(-x)); }
#define LDM4(r, a) \
    asm volatile("ldmatrix.sync.aligned.m8n8.x4.shared.b16 {%0,%1,%2,%3}, [%4];" \
        : "=r"((r)[0]), "=r"((r)[1]), "=r"((r)[2]), "=r"((r)[3]) : "r"(a))
#define MMAF32(c, a, b0, b1) \
    asm volatile("mma.sync.aligned.m16n8k16.row.col.f32.f16.f16.f32 " \
        "{%0,%1,%2,%3}, {%4,%5,%6,%7}, {%8,%9}, {%0,%1,%2,%3};" \
        : "+f"((c)[0]), "+f"((c)[1]), "+f"((c)[2]), "+f"((c)[3]) \
        : "r"((a)[0]), "r"((a)[1]), "r"((a)[2]), "r"((a)[3]), "r"(b0), "r"(b1))
#define CPA16(d, s, n) \
    asm volatile("cp.async.cg.shared.global [%0], [%1], 16, %2;" :: "r"(d), "l"(s), "r"(n) : "memory")
#define CPA_COMMIT() asm volatile("cp.async.commit_group;" ::: "memory")
#define CPA_WAIT2()  asm volatile("cp.async.wait_group 2;" ::: "memory")

// ================= conversions =================
__global__ void __launch_bounds__(256) convW(const float* __restrict__ src,
                                             __half* __restrict__ dh, int K) {
    int row = blockIdx.x, tid = threadIdx.x;
    const float* s = src + (size_t)row * K;
    for (int i = tid * 4; i < K; i += 1024) {
        float4 v = *(const float4*)(s + i);
        *(uint2*)(dh + (size_t)row * K + i) = make_uint2(h2only(v.x, v.y), h2only(v.z, v.w));
    }
}
// Q weight (remapped) -> rows 0..2047 of c_qkvw
__global__ void __launch_bounds__(256) convQ(const float* __restrict__ qw) {
    int n = blockIdx.x, tid = threadIdx.x;
    const float* s = qw + (size_t)((n >> 7) * 192 + (n & 127)) * 2048;
    for (int i = tid * 4; i < 2048; i += 1024) {
        float4 v = *(const float4*)(s + i);
        *(uint2*)(c_qkvw + (size_t)n * 2048 + i) = make_uint2(h2only(v.x, v.y), h2only(v.z, v.w));
    }
}
// KV weight -> rows 2048..6143 of c_qkvw
__global__ void __launch_bounds__(256) convKV(const float* __restrict__ kvw) {
    int n = blockIdx.x, tid = threadIdx.x;
    const float* s = kvw + (size_t)n * 2048;
    for (int i = tid * 4; i < 2048; i += 1024) {
        float4 v = *(const float4*)(s + i);
        *(uint2*)(c_qkvw + (size_t)(n + 2048) * 2048 + i) = make_uint2(h2only(v.x, v.y), h2only(v.z, v.w));
    }
}
__global__ void __launch_bounds__(256) convPair(const float* __restrict__ src,
                                                __half* __restrict__ dh,
                                                int K, int I) {
    int n = blockIdx.x, tid = threadIdx.x;
    int twoI = 2 * I;
    int e = n / twoI, r = n % twoI;
    int sr = (r & 1) ? (I + (r >> 1)) : (r >> 1);
    const float* s = src + ((size_t)e * twoI + sr) * K;
    for (int i = tid * 4; i < K; i += 1024) {
        float4 v = *(const float4*)(s + i);
        *(uint2*)(dh + (size_t)n * K + i) = make_uint2(h2only(v.x, v.y), h2only(v.z, v.w));
    }
}

// ================= HMMA fp16 GEMM (4-stage ring, occupancy 1) =================
// EPI: 0 = f32 out, 1 = f32 out + addsrc, 2 = fp16 out, 3 = silu(g)*u fp16 out (paired cols)
#define GSMEM_BYTES (4 * 20480)

template <int MODE, int EPI>
__global__ void __launch_bounds__(256, 1) gemm_h(
    const __half* __restrict__ Ahp, long long aestride, int lda,
    const __half* __restrict__ Bhp, long long bestride,
    void* __restrict__ C, long long cstride, int ldc,
    int M, int K,
    const float* __restrict__ addsrc, int ldadd)
{
    extern __shared__ char smem[];
    const int e  = blockIdx.z;
    const int Me = (MODE == 0) ? M : g_cnt[e];
    const int bm = blockIdx.y * 128, bn = blockIdx.x * 128;
    if (bm >= Me) return;
    const __half* AhB = Ahp + (MODE == 2 ? (long long)e * aestride : 0LL);
    const __half* BhB = Bhp + (long long)e * bestride;

    const uint32_t sb = smem_u32(smem);
    const int tid = threadIdx.x, wid = tid >> 5, lid = tid & 31;
    const int wm = wid & 3, wn = wid >> 2;

    uint32_t sOff[2]; uint32_t aval[2];
    const char *aHp[2], *bHp[2];
    #pragma unroll
    for (int i = 0; i < 2; i++) {
        int q = tid + i * 256;
        int row = q >> 2, seg = q & 3;
        sOff[i] = (uint32_t)(row * 80 + seg * 16);
        int gm = bm + row;
        aval[i] = (gm < Me) ? 16u : 0u;
        long long arow;
        if (MODE == 1) arow = (gm < Me) ? (long long)g_tok[e * T_TOK + gm] : 0LL;
        else           arow = (gm < Me) ? (long long)gm : 0LL;
        aHp[i] = (const char*)(AhB + arow * (long long)lda) + seg * 16;
        long long brow = (long long)(bn + row);
        bHp[i] = (const char*)(BhB + brow * (long long)lda) + seg * 16;
    }

    const int laneRow = lid & 15, laneChk = lid >> 4;
    uint32_t aOff[2], bOff[4];
    #pragma unroll
    for (int t = 0; t < 2; t++)
        aOff[t] = (uint32_t)((wm * 32 + t * 16 + laneRow) * 80 + laneChk * 16);
    #pragma unroll
    for (int p = 0; p < 4; p++)
        bOff[p] = (uint32_t)(10240 + (wn * 64 + p * 16 + laneRow) * 80 + laneChk * 16);

    float am[2][8][4];
    #pragma unroll
    for (int t = 0; t < 2; t++)
        #pragma unroll
        for (int n8 = 0; n8 < 8; n8++)
            #pragma unroll
            for (int j = 0; j < 4; j++) am[t][n8][j] = 0.f;

    const int NC = K / 32;

    #define ISSUE(c) do { \
        uint32_t st_ = sb + (uint32_t)((c) & 3) * 20480u; \
        long long kb_ = (long long)(c) * 64; \
        _Pragma("unroll") \
        for (int i_ = 0; i_ < 2; i_++) { \
            CPA16(st_ + sOff[i_],          aHp[i_] + kb_, aval[i_]); \
            CPA16(st_ + 10240u + sOff[i_], bHp[i_] + kb_, 16u); \
        } \
    } while (0)

    ISSUE(0); CPA_COMMIT();
    if (NC > 1) { ISSUE(1); } CPA_COMMIT();
    if (NC > 2) { ISSUE(2); } CPA_COMMIT();

    for (int c = 0; c < NC; c++) {
        CPA_WAIT2();
        __syncthreads();
        const uint32_t stg = sb + (uint32_t)(c & 3) * 20480u;
        #pragma unroll
        for (int h = 0; h < 2; h++) {
            uint32_t ah0[4], ah1[4];
            LDM4(ah0, stg + aOff[0] + h * 32);
            LDM4(ah1, stg + aOff[1] + h * 32);
            #pragma unroll
            for (int p = 0; p < 4; p++) {
                uint32_t bh[4];
                LDM4(bh, stg + bOff[p] + h * 32);
                MMAF32(am[0][2 * p],     ah0, bh[0], bh[2]);
                MMAF32(am[0][2 * p + 1], ah0, bh[1], bh[3]);
                MMAF32(am[1][2 * p],     ah1, bh[0], bh[2]);
                MMAF32(am[1][2 * p + 1], ah1, bh[1], bh[3]);
            }
        }
        __syncthreads();
        if (c + 3 < NC) ISSUE(c + 3);
        CPA_COMMIT();
    }
    #undef ISSUE

    const int g = lid >> 2, tg = lid & 3;
    #pragma unroll
    for (int t = 0; t < 2; t++) {
        #pragma unroll
        for (int half = 0; half < 2; half++) {
            int row = bm + wm * 32 + t * 16 + g + half * 8;
            if (row >= Me) continue;
            #pragma unroll
            for (int n8 = 0; n8 < 8; n8++) {
                float v0 = am[t][n8][half * 2], v1 = am[t][n8][half * 2 + 1];
                if (EPI == 3) {
                    long long idx = (long long)e * cstride + (long long)row * ldc
                                  + (bn >> 1) + wn * 32 + n8 * 4 + tg;
                    ((__half*)C)[idx] = __float2half_rn(silu_f(v0) * v1);
                } else {
                    long long base = (long long)e * cstride + (long long)row * ldc
                                   + bn + wn * 64 + tg * 2 + n8 * 8;
                    if (EPI == 1) {
                        const float* ap = addsrc + (long long)row * ldadd + bn + wn * 64 + tg * 2 + n8 * 8;
                        v0 += ap[0]; v1 += ap[1];
                    }
                    if (EPI == 2) *(uint32_t*)((__half*)C + base) = h2only(v0, v1);
                    else { float* cp = (float*)C + base; cp[0] = v0; cp[1] = v1; }
                }
            }
        }
    }
}

// ---------------- rmsnorm (optional fp32 out + fp16 plane) ----------------
__global__ __launch_bounds__(256) void rmsnorm_h(const float* __restrict__ in,
                                                 const float* __restrict__ w,
                                                 float* __restrict__ out,
                                                 __half* __restrict__ ph) {
    __shared__ float red[8];
    int t = blockIdx.x, tid = threadIdx.x;
    const float* row = in + (size_t)t * H_DIM;
    float ss = 0.f;
    for (int i = tid; i < H_DIM; i += 256) { float v = row[i]; ss += v * v; }
    #pragma unroll
    for (int o = 16; o; o >>= 1) ss += __shfl_xor_sync(0xffffffffu, ss, o);
    if ((tid & 31) == 0) red[tid >> 5] = ss;
    __syncthreads();
    float tot = red[0] + red[1] + red[2] + red[3] + red[4] + red[5] + red[6] + red[7];
    float inv = rsqrtf(tot * (1.0f / H_DIM) + 1e-6f);
    for (int i = tid * 2; i < H_DIM; i += 512) {
        float a = row[i] * inv * w[i];
        float b = row[i + 1] * inv * w[i + 1];
        if (out) { out[(size_t)t * H_DIM + i] = a; out[(size_t)t * H_DIM + i + 1] = b; }
        ((uint32_t*)ph)[((size_t)t * H_DIM + i) >> 1] = h2only(a, b);
    }
}

// ---------------- HMMA flash attention (heavy tiles first) ----------------
#define ATTN_SMEM 81920

__global__ void __launch_bounds__(256) attn_mma() {
    extern __shared__ char smem[];
    const uint32_t sb = smem_u32(smem);
    const uint32_t QS = 0, KS = 17408, VT = 34816, PF = 53248;
    float* Ps   = (float*)(smem + 62464);
    float* mrow = (float*)(smem + 79104);
    float* lrow = (float*)(smem + 79360);
    float* corr = (float*)(smem + 79616);
    float* pm4  = (float*)(smem + 79872);
    float* ps4  = (float*)(smem + 80896);
    __half* Vt  = (__half*)(smem + VT);
    __half* Pf  = (__half*)(smem + PF);

    int bh = blockIdx.y; int b = bh >> 4, h = bh & 15;
    int qt = 15 - blockIdx.x;
    int q0 = qt * 64;
    int tb = b * S_LEN;
    int tid = threadIdx.x, wid = tid >> 5, lid = tid & 31;
    int wm = wid & 3, wn = wid >> 2;
    const int laneRow = lid & 15, laneChk = lid >> 4;
    const int g = lid >> 2, tg = lid & 3;
    const float scale = 1.0f / sqrtf(192.0f);

    for (int i = tid; i < 1024; i += 256) {
        int r = i >> 4, c8 = i & 15;
        uint4 v = *(const uint4*)(c_qkvo + (size_t)(tb + q0 + r) * 6144 + h * 128 + c8 * 8);
        *(uint4*)(smem + QS + r * 272 + c8 * 16) = v;
    }
    if (tid < 64) { mrow[tid] = -1e30f; lrow[tid] = 0.f; }

    float acc[8][4];
    #pragma unroll
    for (int n8 = 0; n8 < 8; n8++)
        #pragma unroll
        for (int j = 0; j < 4; j++) acc[n8][j] = 0.f;
    __syncthreads();

    int nkt = qt + 1;
    for (int kt = 0; kt < nkt; kt++) {
        int k0 = kt * 64;
        for (int i = tid; i < 1024; i += 256) {
            int r = i >> 4, c8 = i & 15;
            uint4 v = *(const uint4*)(c_qkvo + (size_t)(tb + k0 + r) * 6144 + 2048 + h * 128 + c8 * 8);
            *(uint4*)(smem + KS + r * 272 + c8 * 16) = v;
        }
        #pragma unroll
        for (int it = 0; it < 4; it++) {
            int u = tid + it * 256;
            int key = (u & 15) | ((u >> 8) << 4);
            int d8 = (u >> 4) & 15;
            uint4 v = *(const uint4*)(c_qkvo + (size_t)(tb + k0 + key) * 6144 + 4096 + h * 128 + d8 * 8);
            __half* hv = (__half*)&v;
            #pragma unroll
            for (int j = 0; j < 8; j++) Vt[(d8 * 8 + j) * 72 + key] = hv[j];
        }
        __syncthreads();

        float sc[4][4];
        #pragma unroll
        for (int f = 0; f < 4; f++)
            #pragma unroll
            for (int j = 0; j < 4; j++) sc[f][j] = 0.f;
        #pragma unroll
        for (int h8 = 0; h8 < 8; h8++) {
            uint32_t aq[4];
            LDM4(aq, sb + QS + (wm * 16 + laneRow) * 272 + h8 * 32 + laneChk * 16);
            #pragma unroll
            for (int p16 = 0; p16 < 2; p16++) {
                uint32_t bk[4];
                LDM4(bk, sb + KS + (wn * 32 + p16 * 16 + laneRow) * 272 + h8 * 32 + laneChk * 16);
                MMAF32(sc[p16 * 2],     aq, bk[0], bk[2]);
                MMAF32(sc[p16 * 2 + 1], aq, bk[1], bk[3]);
            }
        }
        {
            int r0 = wm * 16 + g, r1 = r0 + 8;
            int gr0 = q0 + r0, gr1 = q0 + r1;
            #pragma unroll
            for (int f = 0; f < 4; f++) {
                int cb = wn * 32 + (f >> 1) * 16 + (f & 1) * 8 + tg * 2;
                int ck = k0 + cb;
                Ps[r0 * 65 + cb]     = (ck     <= gr0) ? sc[f][0] * scale : -1e30f;
                Ps[r0 * 65 + cb + 1] = (ck + 1 <= gr0) ? sc[f][1] * scale : -1e30f;
                Ps[r1 * 65 + cb]     = (ck     <= gr1) ? sc[f][2] * scale : -1e30f;
                Ps[r1 * 65 + cb + 1] = (ck + 1 <= gr1) ? sc[f][3] * scale : -1e30f;
            }
        }
        __syncthreads();

        {
            int r = tid & 63, qd = tid >> 6;
            float m0 = mrow[r];
            float pm = -1e30f;
            #pragma unroll 4
            for (int c = qd * 16; c < qd * 16 + 16; c++) pm = fmaxf(pm, Ps[r * 65 + c]);
            pm4[r * 4 + qd] = pm;
            __syncthreads();
            float mx = fmaxf(m0, fmaxf(fmaxf(pm4[r * 4], pm4[r * 4 + 1]),
                                       fmaxf(pm4[r * 4 + 2], pm4[r * 4 + 3])));
            float sum = 0.f;
            #pragma unroll 4
            for (int c = qd * 16; c < qd * 16 + 16; c++) {
                float p = __expf(Ps[r * 65 + c] - mx);
                sum += p;
                Pf[r * 72 + c] = __float2half_rn(p);
            }
            ps4[r * 4 + qd] = sum;
            __syncthreads();
            if (qd == 0) {
                float cr = __expf(m0 - mx);
                corr[r] = cr;
                lrow[r] = lrow[r] * cr + ps4[r * 4] + ps4[r * 4 + 1] + ps4[r * 4 + 2] + ps4[r * 4 + 3];
                mrow[r] = mx;
            }
        }
        __syncthreads();

        {
            float cr0 = corr[wm * 16 + g], cr1 = corr[wm * 16 + g + 8];
            #pragma unroll
            for (int n8 = 0; n8 < 8; n8++) {
                acc[n8][0] *= cr0; acc[n8][1] *= cr0;
                acc[n8][2] *= cr1; acc[n8][3] *= cr1;
            }
        }
        #pragma unroll
        for (int kh = 0; kh < 4; kh++) {
            uint32_t ap[4];
            LDM4(ap, sb + PF + (wm * 16 + laneRow) * 144 + kh * 32 + laneChk * 16);
            #pragma unroll
            for (int p16 = 0; p16 < 4; p16++) {
                uint32_t bv[4];
                LDM4(bv, sb + VT + (wn * 64 + p16 * 16 + laneRow) * 144 + kh * 32 + laneChk * 16);
                MMAF32(acc[p16 * 2],     ap, bv[0], bv[2]);
                MMAF32(acc[p16 * 2 + 1], ap, bv[1], bv[3]);
            }
        }
        __syncthreads();
    }

    {
        int r0 = wm * 16 + g, r1 = r0 + 8;
        float i0 = 1.0f / lrow[r0], i1 = 1.0f / lrow[r1];
        size_t b0 = (size_t)(tb + q0 + r0) * 2048 + h * 128;
        size_t b1 = (size_t)(tb + q0 + r1) * 2048 + h * 128;
        #pragma unroll
        for (int n8 = 0; n8 < 8; n8++) {
            int col = wn * 64 + (n8 >> 1) * 16 + (n8 & 1) * 8 + tg * 2;
            *(uint32_t*)(c_ath + b0 + col) = h2only(acc[n8][0] * i0, acc[n8][1] * i0);
            *(uint32_t*)(c_ath + b1 + col) = h2only(acc[n8][2] * i1, acc[n8][3] * i1);
        }
    }
}

// ---------------- gate ----------------
__global__ void __launch_bounds__(512) zero_cnt() { if (threadIdx.x < E_NUM) g_cnt[threadIdx.x] = 0; }

__global__ void __launch_bounds__(512) gate_kernel(const float* __restrict__ gate_w) {
    int t = blockIdx.x;
    int w = threadIdx.x >> 5, lane = threadIdx.x & 31;
    const float* x = g_X2 + (size_t)t * H_DIM;
    const float* gw = gate_w + (size_t)w * H_DIM;
    float s = 0.f;
    for (int i = lane; i < H_DIM; i += 32) s += x[i] * gw[i];
    #pragma unroll
    for (int o = 16; o; o >>= 1) s += __shfl_xor_sync(0xffffffffu, s, o);
    __shared__ float lg[E_NUM];
    if (lane == 0) lg[w] = s;
    __syncthreads();
    if (threadIdx.x == 0) {
        float mx = -1e30f;
        for (int e = 0; e < E_NUM; e++) mx = fmaxf(mx, lg[e]);
        float pe[E_NUM];
        for (int e = 0; e < E_NUM; e++) pe[e] = expf(lg[e] - mx);
        bool used[E_NUM];
        for (int e = 0; e < E_NUM; e++) used[e] = false;
        int sel[4]; float sw[4]; float wsum = 0.f;
        for (int j = 0; j < 4; j++) {
            int bi = -1; float bv = -1.f;
            for (int e = 0; e < E_NUM; e++)
                if (!used[e] && pe[e] > bv) { bv = pe[e]; bi = e; }
            used[bi] = true; sel[j] = bi; sw[j] = bv; wsum += bv;
        }
        for (int j = 0; j < 4; j++) {
            int e = sel[j];
            int pos = atomicAdd(&g_cnt[e], 1);
            g_tok[e * T_TOK + pos] = t;
            g_texp[t * 4 + j] = e;
            g_trow[t * 4 + j] = pos;
            g_twt [t * 4 + j] = sw[j] / wsum;
        }
    }
}

// ---------------- final sum (fp16 down planes) ----------------
__global__ void __launch_bounds__(256) final_sum(float* __restrict__ out) {
    int t = blockIdx.x;
    int e0 = g_texp[t * 4 + 0], e1 = g_texp[t * 4 + 1], e2 = g_texp[t * 4 + 2], e3 = g_texp[t * 4 + 3];
    int r0 = g_trow[t * 4 + 0], r1 = g_trow[t * 4 + 1], r2 = g_trow[t * 4 + 2], r3 = g_trow[t * 4 + 3];
    float w0 = g_twt[t * 4 + 0], w1v = g_twt[t * 4 + 1], w2v = g_twt[t * 4 + 2], w3 = g_twt[t * 4 + 3];
    const __half* d0 = c_down + ((size_t)e0 * T_TOK + r0) * H_DIM;
    const __half* d1 = c_down + ((size_t)e1 * T_TOK + r1) * H_DIM;
    const __half* d2 = c_down + ((size_t)e2 * T_TOK + r2) * H_DIM;
    const __half* d3 = c_down + ((size_t)e3 * T_TOK + r3) * H_DIM;
    for (int h = threadIdx.x * 2; h < H_DIM; h += 512) {
        float2 a0 = __half22float2(*(const __half2*)(d0 + h));
        float2 a1 = __half22float2(*(const __half2*)(d1 + h));
        float2 a2 = __half22float2(*(const __half2*)(d2 + h));
        float2 a3 = __half22float2(*(const __half2*)(d3 + h));
        float* o = out + (size_t)t * H_DIM + h;
        o[0] += w0 * a0.x + w1v * a1.x + w2v * a2.x + w3 * a3.x;
        o[1] += w0 * a0.y + w1v * a1.y + w2v * a2.y + w3 * a3.y;
    }
}

// ---------------- launch ----------------
extern "C" void kernel_launch(void* const* d_in, const int* in_sizes, int n_in,
                              void* d_out, int out_size) {
    (void)in_sizes; (void)n_in; (void)out_size;
    const float* hidden  = (const float*)d_in[0];
    const float* ln1_w   = (const float*)d_in[2];
    const float* ln2_w   = (const float*)d_in[3];
    const float* q_w     = (const float*)d_in[4];
    const float* kv_w    = (const float*)d_in[5];
    const float* o_w     = (const float*)d_in[6];
    const float* gate_w  = (const float*)d_in[7];
    const float* w1      = (const float*)d_in[8];
    const float* w2      = (const float*)d_in[9];
    const float* sh_gu_w = (const float*)d_in[10];
    const float* sh_dn_w = (const float*)d_in[11];
    float* out = (float*)d_out;

    static cudaStream_t s1 = nullptr, s2 = nullptr;
    static cudaEvent_t ev[14];
    if (!s1) {
        cudaStreamCreateWithFlags(&s1, cudaStreamNonBlocking);
        cudaStreamCreateWithFlags(&s2, cudaStreamNonBlocking);
        for (int i = 0; i < 14; i++) cudaEventCreateWithFlags(&ev[i], cudaEventDisableTiming);
    }

    float *pHid, *pX2;
    cudaGetSymbolAddress((void**)&pHid, g_hid);
    cudaGetSymbolAddress((void**)&pX2, g_X2);

    __half *Xh, *qkvo, *ath, *X2h, *guh, *sah, *down;
    __half *qkvw, *owh, *w1h, *w2h, *sgh, *sdh;
    cudaGetSymbolAddress((void**)&Xh, c_Xh);
    cudaGetSymbolAddress((void**)&qkvo, c_qkvo);
    cudaGetSymbolAddress((void**)&ath, c_ath);
    cudaGetSymbolAddress((void**)&X2h, c_X2h);
    cudaGetSymbolAddress((void**)&guh, c_guh);
    cudaGetSymbolAddress((void**)&sah, c_sah);
    cudaGetSymbolAddress((void**)&down, c_down);
    cudaGetSymbolAddress((void**)&qkvw, c_qkvw);
    cudaGetSymbolAddress((void**)&owh, c_owh);
    cudaGetSymbolAddress((void**)&w1h, c_w1h);
    cudaGetSymbolAddress((void**)&w2h, c_w2h);
    cudaGetSymbolAddress((void**)&sgh, c_sgh);
    cudaGetSymbolAddress((void**)&sdh, c_sdh);

    cudaFuncSetAttribute(attn_mma, cudaFuncAttributeMaxDynamicSharedMemorySize, ATTN_SMEM);
    cudaFuncSetAttribute(gemm_h<0, 1>, cudaFuncAttributeMaxDynamicSharedMemorySize, GSMEM_BYTES);
    cudaFuncSetAttribute(gemm_h<0, 2>, cudaFuncAttributeMaxDynamicSharedMemorySize, GSMEM_BYTES);
    cudaFuncSetAttribute(gemm_h<0, 3>, cudaFuncAttributeMaxDynamicSharedMemorySize, GSMEM_BYTES);
    cudaFuncSetAttribute(gemm_h<1, 3>, cudaFuncAttributeMaxDynamicSharedMemorySize, GSMEM_BYTES);
    cudaFuncSetAttribute(gemm_h<2, 2>, cudaFuncAttributeMaxDynamicSharedMemorySize, GSMEM_BYTES);

    // fork side streams
    cudaEventRecord(ev[0], 0);
    cudaStreamWaitEvent(s1, ev[0], 0);
    cudaStreamWaitEvent(s2, ev[0], 0);

    // s1: conversions — Q first (unblocks Q-GEMM early), then KV, then the rest
    convQ<<<2048, 256, 0, s1>>>(q_w);                             cudaEventRecord(ev[1], s1);
    convKV<<<4096, 256, 0, s1>>>(kv_w);                           cudaEventRecord(ev[2], s1);
    convW<<<2048, 256, 0, s1>>>(o_w, owh, 2048);                  cudaEventRecord(ev[3], s1);
    convPair<<<E_NUM * TWO_I, 256, 0, s1>>>(w1, w1h, 2048, I_DIM);   cudaEventRecord(ev[4], s1);
    convPair<<<SH2, 256, 0, s1>>>(sh_gu_w, sgh, 2048, SHI_DIM);   cudaEventRecord(ev[5], s1);
    convW<<<E_NUM * H_DIM, 256, 0, s1>>>(w2, w2h, 1408);          cudaEventRecord(ev[6], s1);
    convW<<<H_DIM, 256, 0, s1>>>(sh_dn_w, sdh, 2816);             cudaEventRecord(ev[7], s1);

    // s0: rmsnorm -> fp16 X plane
    rmsnorm_h<<<T_TOK, 256>>>(hidden, ln1_w, nullptr, Xh);
    cudaEventRecord(ev[10], 0);   // X plane ready

    // s2: KV projection (columns 2048..6143 of c_qkvo), concurrent with Q proj on s0
    cudaStreamWaitEvent(s2, ev[10], 0);
    cudaStreamWaitEvent(s2, ev[2], 0);
    gemm_h<0, 2><<<dim3(32, 16, 1), 256, GSMEM_BYTES, s2>>>(
        Xh, 0LL, 2048, qkvw + (size_t)2048 * 2048, 0LL,
        qkvo + 2048, 0LL, 6144, T_TOK, 2048, nullptr, 0);
    cudaEventRecord(ev[11], s2);

    // s0: Q projection (columns 0..2047 of c_qkvo)
    cudaStreamWaitEvent(0, ev[1], 0);
    gemm_h<0, 2><<<dim3(16, 16, 1), 256, GSMEM_BYTES>>>(
        Xh, 0LL, 2048, qkvw, 0LL, qkvo, 0LL, 6144, T_TOK, 2048, nullptr, 0);

    // s0: attention (needs Q + KV)
    cudaStreamWaitEvent(0, ev[11], 0);
    attn_mma<<<dim3(16, 32), 256, ATTN_SMEM>>>();

    // s0: hid = attn @ o_w^T + hidden
    cudaStreamWaitEvent(0, ev[3], 0);
    gemm_h<0, 1><<<dim3(16, 16, 1), 256, GSMEM_BYTES>>>(
        ath, 0LL, 2048, owh, 0LL, pHid, 0LL, H_DIM, T_TOK, 2048, hidden, H_DIM);
    rmsnorm_h<<<T_TOK, 256>>>(pHid, ln2_w, pX2, X2h);
    cudaEventRecord(ev[8], 0);

    // s2: routed branch
    cudaStreamWaitEvent(s2, ev[8], 0);
    zero_cnt<<<1, 32, 0, s2>>>();
    gate_kernel<<<T_TOK, 512, 0, s2>>>(gate_w);
    cudaStreamWaitEvent(s2, ev[4], 0);
    gemm_h<1, 3><<<dim3(22, 16, E_NUM), 256, GSMEM_BYTES, s2>>>(
        X2h, 0LL, 2048, w1h, (long long)TWO_I * H_DIM,
        guh, (long long)T_TOK * I_DIM, I_DIM, 0, 2048, nullptr, 0);
    cudaStreamWaitEvent(s2, ev[6], 0);
    gemm_h<2, 2><<<dim3(16, 16, E_NUM), 256, GSMEM_BYTES, s2>>>(
        guh, (long long)T_TOK * I_DIM, 1408, w2h, (long long)H_DIM * I_DIM,
        down, (long long)T_TOK * H_DIM, H_DIM, 0, 1408, nullptr, 0);
    cudaEventRecord(ev[9], s2);

    // s0: shared branch
    cudaStreamWaitEvent(0, ev[5], 0);
    gemm_h<0, 3><<<dim3(44, 16, 1), 256, GSMEM_BYTES>>>(
        X2h, 0LL, 2048, sgh, 0LL, sah, 0LL, SHI_DIM, T_TOK, 2048, nullptr, 0);
    cudaStreamWaitEvent(0, ev[7], 0);
    gemm_h<0, 1><<<dim3(16, 16, 1), 256, GSMEM_BYTES>>>(
        sah, 0LL, 2816, sdh, 0LL, out, 0LL, H_DIM, T_TOK, 2816, pHid, H_DIM);

    // join routed, final combine
    cudaStreamWaitEvent(0, ev[9], 0);
    final_sum<<<T_TOK, 256>>>(out);
}

// round 17
// speedup vs baseline: 1.4685x; 1.0014x over previous
#include <cuda_runtime.h>
#include <cuda_fp16.h>
#include <cstdint>
#include <math.h>

#define T_TOK 2048
#define H_DIM 2048
#define S_LEN 1024
#define E_NUM 16
#define I_DIM 1408
#define TWO_I 2816
#define SHI_DIM 2816
#define SH2 5632

// ---------------- fp32 scratch ----------------
__device__ float g_hid [(size_t)T_TOK * H_DIM];
__device__ float g_X2  [(size_t)T_TOK * H_DIM];
__device__ int   g_cnt [E_NUM];
__device__ int   g_tok [E_NUM * T_TOK];
__device__ int   g_texp[T_TOK * 4];
__device__ int   g_trow[T_TOK * 4];
__device__ float g_twt [T_TOK * 4];

// ---------------- fp16 planes ----------------
__device__ __half c_Xh  [(size_t)T_TOK * H_DIM];
__device__ __half c_qkvo[(size_t)T_TOK * 6144];
__device__ __half c_ath [(size_t)T_TOK * 2048];
__device__ __half c_X2h [(size_t)T_TOK * H_DIM];
__device__ __half c_guh [(size_t)E_NUM * T_TOK * I_DIM];
__device__ __half c_sah [(size_t)T_TOK * SHI_DIM];
__device__ __half c_down[(size_t)E_NUM * T_TOK * H_DIM];
__device__ __half c_qkvw[(size_t)6144 * 2048];
__device__ __half c_owh [(size_t)2048 * 2048];
__device__ __half c_w1h [(size_t)E_NUM * TWO_I * H_DIM];
__device__ __half c_w2h [(size_t)E_NUM * H_DIM * I_DIM];
__device__ __half c_sgh [(size_t)SH2 * H_DIM];
__device__ __half c_sdh [(size_t)H_DIM * SHI_DIM];

// ================= helpers =================
static __device__ __forceinline__ uint32_t smem_u32(const void* p) {
    uint32_t a;
    asm("{ .reg .u64 t; cvta.to.shared.u64 t, %1; cvt.u32.u64 %0, t; }" : "=r"(a) : "l"(p));
    return a;
}
static __device__ __forceinline__ uint32_t h2only(float x, float y) {
    __half2 hp = __halves2half2(__float2half_rn(x), __float2half_rn(y));
    return *(uint32_t*)&hp;
}
__device__ __forceinline__ float silu_f(float x) { return x / (1.0f + __expf(-x)); }
#define LDM4(r, a) \
    asm volatile("ldmatrix.sync.aligned.m8n8.x4.shared.b16 {%0,%1,%2,%3}, [%4];" \
        : "=r"((r)[0]), "=r"((r)[1]), "=r"((r)[2]), "=r"((r)[3]) : "r"(a))
#define MMAF32(c, a, b0, b1) \
    asm volatile("mma.sync.aligned.m16n8k16.row.col.f32.f16.f16.f32 " \
        "{%0,%1,%2,%3}, {%4,%5,%6,%7}, {%8,%9}, {%0,%1,%2,%3};" \
        : "+f"((c)[0]), "+f"((c)[1]), "+f"((c)[2]), "+f"((c)[3]) \
        : "r"((a)[0]), "r"((a)[1]), "r"((a)[2]), "r"((a)[3]), "r"(b0), "r"(b1))
#define CPA16(d, s, n) \
    asm volatile("cp.async.cg.shared.global [%0], [%1], 16, %2;" :: "r"(d), "l"(s), "r"(n) : "memory")
#define CPA_COMMIT() asm volatile("cp.async.commit_group;" ::: "memory")
#define CPA_WAIT2()  asm volatile("cp.async.wait_group 2;" ::: "memory")

// ================= conversions =================
__global__ void __launch_bounds__(256) convW(const float* __restrict__ src,
                                             __half* __restrict__ dh, int K) {
    int row = blockIdx.x, tid = threadIdx.x;
    const float* s = src + (size_t)row * K;
    for (int i = tid * 4; i < K; i += 1024) {
        float4 v = *(const float4*)(s + i);
        *(uint2*)(dh + (size_t)row * K + i) = make_uint2(h2only(v.x, v.y), h2only(v.z, v.w));
    }
}
// Q weight (remapped) -> rows 0..2047 of c_qkvw
__global__ void __launch_bounds__(256) convQ(const float* __restrict__ qw) {
    int n = blockIdx.x, tid = threadIdx.x;
    const float* s = qw + (size_t)((n >> 7) * 192 + (n & 127)) * 2048;
    for (int i = tid * 4; i < 2048; i += 1024) {
        float4 v = *(const float4*)(s + i);
        *(uint2*)(c_qkvw + (size_t)n * 2048 + i) = make_uint2(h2only(v.x, v.y), h2only(v.z, v.w));
    }
}
// KV weight -> rows 2048..6143 of c_qkvw
__global__ void __launch_bounds__(256) convKV(const float* __restrict__ kvw) {
    int n = blockIdx.x, tid = threadIdx.x;
    const float* s = kvw + (size_t)n * 2048;
    for (int i = tid * 4; i < 2048; i += 1024) {
        float4 v = *(const float4*)(s + i);
        *(uint2*)(c_qkvw + (size_t)(n + 2048) * 2048 + i) = make_uint2(h2only(v.x, v.y), h2only(v.z, v.w));
    }
}
__global__ void __launch_bounds__(256) convPair(const float* __restrict__ src,
                                                __half* __restrict__ dh,
                                                int K, int I) {
    int n = blockIdx.x, tid = threadIdx.x;
    int twoI = 2 * I;
    int e = n / twoI, r = n % twoI;
    int sr = (r & 1) ? (I + (r >> 1)) : (r >> 1);
    const float* s = src + ((size_t)e * twoI + sr) * K;
    for (int i = tid * 4; i < K; i += 1024) {
        float4 v = *(const float4*)(s + i);
        *(uint2*)(dh + (size_t)n * K + i) = make_uint2(h2only(v.x, v.y), h2only(v.z, v.w));
    }
}

// ================= HMMA fp16 GEMM (4-stage ring, occupancy 1) =================
// EPI: 0 = f32 out, 1 = f32 out + addsrc, 2 = fp16 out, 3 = silu(g)*u fp16 out (paired cols)
#define GSMEM_BYTES (4 * 20480)

template <int MODE, int EPI>
__global__ void __launch_bounds__(256, 1) gemm_h(
    const __half* __restrict__ Ahp, long long aestride, int lda,
    const __half* __restrict__ Bhp, long long bestride,
    void* __restrict__ C, long long cstride, int ldc,
    int M, int K,
    const float* __restrict__ addsrc, int ldadd)
{
    extern __shared__ char smem[];
    const int e  = blockIdx.z;
    const int Me = (MODE == 0) ? M : g_cnt[e];
    const int bm = blockIdx.y * 128, bn = blockIdx.x * 128;
    if (bm >= Me) return;
    const __half* AhB = Ahp + (MODE == 2 ? (long long)e * aestride : 0LL);
    const __half* BhB = Bhp + (long long)e * bestride;

    const uint32_t sb = smem_u32(smem);
    const int tid = threadIdx.x, wid = tid >> 5, lid = tid & 31;
    const int wm = wid & 3, wn = wid >> 2;

    uint32_t sOff[2]; uint32_t aval[2];
    const char *aHp[2], *bHp[2];
    #pragma unroll
    for (int i = 0; i < 2; i++) {
        int q = tid + i * 256;
        int row = q >> 2, seg = q & 3;
        sOff[i] = (uint32_t)(row * 80 + seg * 16);
        int gm = bm + row;
        aval[i] = (gm < Me) ? 16u : 0u;
        long long arow;
        if (MODE == 1) arow = (gm < Me) ? (long long)g_tok[e * T_TOK + gm] : 0LL;
        else           arow = (gm < Me) ? (long long)gm : 0LL;
        aHp[i] = (const char*)(AhB + arow * (long long)lda) + seg * 16;
        long long brow = (long long)(bn + row);
        bHp[i] = (const char*)(BhB + brow * (long long)lda) + seg * 16;
    }

    const int laneRow = lid & 15, laneChk = lid >> 4;
    uint32_t aOff[2], bOff[4];
    #pragma unroll
    for (int t = 0; t < 2; t++)
        aOff[t] = (uint32_t)((wm * 32 + t * 16 + laneRow) * 80 + laneChk * 16);
    #pragma unroll
    for (int p = 0; p < 4; p++)
        bOff[p] = (uint32_t)(10240 + (wn * 64 + p * 16 + laneRow) * 80 + laneChk * 16);

    float am[2][8][4];
    #pragma unroll
    for (int t = 0; t < 2; t++)
        #pragma unroll
        for (int n8 = 0; n8 < 8; n8++)
            #pragma unroll
            for (int j = 0; j < 4; j++) am[t][n8][j] = 0.f;

    const int NC = K / 32;

    #define ISSUE(c) do { \
        uint32_t st_ = sb + (uint32_t)((c) & 3) * 20480u; \
        long long kb_ = (long long)(c) * 64; \
        _Pragma("unroll") \
        for (int i_ = 0; i_ < 2; i_++) { \
            CPA16(st_ + sOff[i_],          aHp[i_] + kb_, aval[i_]); \
            CPA16(st_ + 10240u + sOff[i_], bHp[i_] + kb_, 16u); \
        } \
    } while (0)

    ISSUE(0); CPA_COMMIT();
    if (NC > 1) { ISSUE(1); } CPA_COMMIT();
    if (NC > 2) { ISSUE(2); } CPA_COMMIT();

    for (int c = 0; c < NC; c++) {
        CPA_WAIT2();
        __syncthreads();
        const uint32_t stg = sb + (uint32_t)(c & 3) * 20480u;
        #pragma unroll
        for (int h = 0; h < 2; h++) {
            uint32_t ah0[4], ah1[4];
            LDM4(ah0, stg + aOff[0] + h * 32);
            LDM4(ah1, stg + aOff[1] + h * 32);
            #pragma unroll
            for (int p = 0; p < 4; p++) {
                uint32_t bh[4];
                LDM4(bh, stg + bOff[p] + h * 32);
                MMAF32(am[0][2 * p],     ah0, bh[0], bh[2]);
                MMAF32(am[0][2 * p + 1], ah0, bh[1], bh[3]);
                MMAF32(am[1][2 * p],     ah1, bh[0], bh[2]);
                MMAF32(am[1][2 * p + 1], ah1, bh[1], bh[3]);
            }
        }
        __syncthreads();
        if (c + 3 < NC) ISSUE(c + 3);
        CPA_COMMIT();
    }
    #undef ISSUE

    const int g = lid >> 2, tg = lid & 3;
    #pragma unroll
    for (int t = 0; t < 2; t++) {
        #pragma unroll
        for (int half = 0; half < 2; half++) {
            int row = bm + wm * 32 + t * 16 + g + half * 8;
            if (row >= Me) continue;
            #pragma unroll
            for (int n8 = 0; n8 < 8; n8++) {
                float v0 = am[t][n8][half * 2], v1 = am[t][n8][half * 2 + 1];
                if (EPI == 3) {
                    long long idx = (long long)e * cstride + (long long)row * ldc
                                  + (bn >> 1) + wn * 32 + n8 * 4 + tg;
                    ((__half*)C)[idx] = __float2half_rn(silu_f(v0) * v1);
                } else {
                    long long base = (long long)e * cstride + (long long)row * ldc
                                   + bn + wn * 64 + tg * 2 + n8 * 8;
                    if (EPI == 1) {
                        const float* ap = addsrc + (long long)row * ldadd + bn + wn * 64 + tg * 2 + n8 * 8;
                        v0 += ap[0]; v1 += ap[1];
                    }
                    if (EPI == 2) *(uint32_t*)((__half*)C + base) = h2only(v0, v1);
                    else { float* cp = (float*)C + base; cp[0] = v0; cp[1] = v1; }
                }
            }
        }
    }
}

// ---------------- rmsnorm (optional fp32 out + fp16 plane) ----------------
__global__ __launch_bounds__(256) void rmsnorm_h(const float* __restrict__ in,
                                                 const float* __restrict__ w,
                                                 float* __restrict__ out,
                                                 __half* __restrict__ ph) {
    __shared__ float red[8];
    int t = blockIdx.x, tid = threadIdx.x;
    const float* row = in + (size_t)t * H_DIM;
    float ss = 0.f;
    for (int i = tid; i < H_DIM; i += 256) { float v = row[i]; ss += v * v; }
    #pragma unroll
    for (int o = 16; o; o >>= 1) ss += __shfl_xor_sync(0xffffffffu, ss, o);
    if ((tid & 31) == 0) red[tid >> 5] = ss;
    __syncthreads();
    float tot = red[0] + red[1] + red[2] + red[3] + red[4] + red[5] + red[6] + red[7];
    float inv = rsqrtf(tot * (1.0f / H_DIM) + 1e-6f);
    for (int i = tid * 2; i < H_DIM; i += 512) {
        float a = row[i] * inv * w[i];
        float b = row[i + 1] * inv * w[i + 1];
        if (out) { out[(size_t)t * H_DIM + i] = a; out[(size_t)t * H_DIM + i + 1] = b; }
        ((uint32_t*)ph)[((size_t)t * H_DIM + i) >> 1] = h2only(a, b);
    }
}

// ---------------- HMMA flash attention (heavy tiles first) ----------------
#define ATTN_SMEM 81920

__global__ void __launch_bounds__(256) attn_mma() {
    extern __shared__ char smem[];
    const uint32_t sb = smem_u32(smem);
    const uint32_t QS = 0, KS = 17408, VT = 34816, PF = 53248;
    float* Ps   = (float*)(smem + 62464);
    float* mrow = (float*)(smem + 79104);
    float* lrow = (float*)(smem + 79360);
    float* corr = (float*)(smem + 79616);
    float* pm4  = (float*)(smem + 79872);
    float* ps4  = (float*)(smem + 80896);
    __half* Vt  = (__half*)(smem + VT);
    __half* Pf  = (__half*)(smem + PF);

    int bh = blockIdx.y; int b = bh >> 4, h = bh & 15;
    int qt = 15 - blockIdx.x;
    int q0 = qt * 64;
    int tb = b * S_LEN;
    int tid = threadIdx.x, wid = tid >> 5, lid = tid & 31;
    int wm = wid & 3, wn = wid >> 2;
    const int laneRow = lid & 15, laneChk = lid >> 4;
    const int g = lid >> 2, tg = lid & 3;
    const float scale = 1.0f / sqrtf(192.0f);

    for (int i = tid; i < 1024; i += 256) {
        int r = i >> 4, c8 = i & 15;
        uint4 v = *(const uint4*)(c_qkvo + (size_t)(tb + q0 + r) * 6144 + h * 128 + c8 * 8);
        *(uint4*)(smem + QS + r * 272 + c8 * 16) = v;
    }
    if (tid < 64) { mrow[tid] = -1e30f; lrow[tid] = 0.f; }

    float acc[8][4];
    #pragma unroll
    for (int n8 = 0; n8 < 8; n8++)
        #pragma unroll
        for (int j = 0; j < 4; j++) acc[n8][j] = 0.f;
    __syncthreads();

    int nkt = qt + 1;
    for (int kt = 0; kt < nkt; kt++) {
        int k0 = kt * 64;
        for (int i = tid; i < 1024; i += 256) {
            int r = i >> 4, c8 = i & 15;
            uint4 v = *(const uint4*)(c_qkvo + (size_t)(tb + k0 + r) * 6144 + 2048 + h * 128 + c8 * 8);
            *(uint4*)(smem + KS + r * 272 + c8 * 16) = v;
        }
        #pragma unroll
        for (int it = 0; it < 4; it++) {
            int u = tid + it * 256;
            int key = (u & 15) | ((u >> 8) << 4);
            int d8 = (u >> 4) & 15;
            uint4 v = *(const uint4*)(c_qkvo + (size_t)(tb + k0 + key) * 6144 + 4096 + h * 128 + d8 * 8);
            __half* hv = (__half*)&v;
            #pragma unroll
            for (int j = 0; j < 8; j++) Vt[(d8 * 8 + j) * 72 + key] = hv[j];
        }
        __syncthreads();

        float sc[4][4];
        #pragma unroll
        for (int f = 0; f < 4; f++)
            #pragma unroll
            for (int j = 0; j < 4; j++) sc[f][j] = 0.f;
        #pragma unroll
        for (int h8 = 0; h8 < 8; h8++) {
            uint32_t aq[4];
            LDM4(aq, sb + QS + (wm * 16 + laneRow) * 272 + h8 * 32 + laneChk * 16);
            #pragma unroll
            for (int p16 = 0; p16 < 2; p16++) {
                uint32_t bk[4];
                LDM4(bk, sb + KS + (wn * 32 + p16 * 16 + laneRow) * 272 + h8 * 32 + laneChk * 16);
                MMAF32(sc[p16 * 2],     aq, bk[0], bk[2]);
                MMAF32(sc[p16 * 2 + 1], aq, bk[1], bk[3]);
            }
        }
        {
            int r0 = wm * 16 + g, r1 = r0 + 8;
            int gr0 = q0 + r0, gr1 = q0 + r1;
            #pragma unroll
            for (int f = 0; f < 4; f++) {
                int cb = wn * 32 + (f >> 1) * 16 + (f & 1) * 8 + tg * 2;
                int ck = k0 + cb;
                Ps[r0 * 65 + cb]     = (ck     <= gr0) ? sc[f][0] * scale : -1e30f;
                Ps[r0 * 65 + cb + 1] = (ck + 1 <= gr0) ? sc[f][1] * scale : -1e30f;
                Ps[r1 * 65 + cb]     = (ck     <= gr1) ? sc[f][2] * scale : -1e30f;
                Ps[r1 * 65 + cb + 1] = (ck + 1 <= gr1) ? sc[f][3] * scale : -1e30f;
            }
        }
        __syncthreads();

        {
            int r = tid & 63, qd = tid >> 6;
            float m0 = mrow[r];
            float pm = -1e30f;
            #pragma unroll 4
            for (int c = qd * 16; c < qd * 16 + 16; c++) pm = fmaxf(pm, Ps[r * 65 + c]);
            pm4[r * 4 + qd] = pm;
            __syncthreads();
            float mx = fmaxf(m0, fmaxf(fmaxf(pm4[r * 4], pm4[r * 4 + 1]),
                                       fmaxf(pm4[r * 4 + 2], pm4[r * 4 + 3])));
            float sum = 0.f;
            #pragma unroll 4
            for (int c = qd * 16; c < qd * 16 + 16; c++) {
                float p = __expf(Ps[r * 65 + c] - mx);
                sum += p;
                Pf[r * 72 + c] = __float2half_rn(p);
            }
            ps4[r * 4 + qd] = sum;
            __syncthreads();
            if (qd == 0) {
                float cr = __expf(m0 - mx);
                corr[r] = cr;
                lrow[r] = lrow[r] * cr + ps4[r * 4] + ps4[r * 4 + 1] + ps4[r * 4 + 2] + ps4[r * 4 + 3];
                mrow[r] = mx;
            }
        }
        __syncthreads();

        {
            float cr0 = corr[wm * 16 + g], cr1 = corr[wm * 16 + g + 8];
            #pragma unroll
            for (int n8 = 0; n8 < 8; n8++) {
                acc[n8][0] *= cr0; acc[n8][1] *= cr0;
                acc[n8][2] *= cr1; acc[n8][3] *= cr1;
            }
        }
        #pragma unroll
        for (int kh = 0; kh < 4; kh++) {
            uint32_t ap[4];
            LDM4(ap, sb + PF + (wm * 16 + laneRow) * 144 + kh * 32 + laneChk * 16);
            #pragma unroll
            for (int p16 = 0; p16 < 4; p16++) {
                uint32_t bv[4];
                LDM4(bv, sb + VT + (wn * 64 + p16 * 16 + laneRow) * 144 + kh * 32 + laneChk * 16);
                MMAF32(acc[p16 * 2],     ap, bv[0], bv[2]);
                MMAF32(acc[p16 * 2 + 1], ap, bv[1], bv[3]);
            }
        }
        __syncthreads();
    }

    {
        int r0 = wm * 16 + g, r1 = r0 + 8;
        float i0 = 1.0f / lrow[r0], i1 = 1.0f / lrow[r1];
        size_t b0 = (size_t)(tb + q0 + r0) * 2048 + h * 128;
        size_t b1 = (size_t)(tb + q0 + r1) * 2048 + h * 128;
        #pragma unroll
        for (int n8 = 0; n8 < 8; n8++) {
            int col = wn * 64 + (n8 >> 1) * 16 + (n8 & 1) * 8 + tg * 2;
            *(uint32_t*)(c_ath + b0 + col) = h2only(acc[n8][0] * i0, acc[n8][1] * i0);
            *(uint32_t*)(c_ath + b1 + col) = h2only(acc[n8][2] * i1, acc[n8][3] * i1);
        }
    }
}

// ---------------- gate ----------------
__global__ void __launch_bounds__(512) zero_cnt() { if (threadIdx.x < E_NUM) g_cnt[threadIdx.x] = 0; }

__global__ void __launch_bounds__(512) gate_kernel(const float* __restrict__ gate_w) {
    int t = blockIdx.x;
    int w = threadIdx.x >> 5, lane = threadIdx.x & 31;
    const float* x = g_X2 + (size_t)t * H_DIM;
    const float* gw = gate_w + (size_t)w * H_DIM;
    float s = 0.f;
    for (int i = lane; i < H_DIM; i += 32) s += x[i] * gw[i];
    #pragma unroll
    for (int o = 16; o; o >>= 1) s += __shfl_xor_sync(0xffffffffu, s, o);
    __shared__ float lg[E_NUM];
    if (lane == 0) lg[w] = s;
    __syncthreads();
    if (threadIdx.x == 0) {
        float mx = -1e30f;
        for (int e = 0; e < E_NUM; e++) mx = fmaxf(mx, lg[e]);
        float pe[E_NUM];
        for (int e = 0; e < E_NUM; e++) pe[e] = expf(lg[e] - mx);
        bool used[E_NUM];
        for (int e = 0; e < E_NUM; e++) used[e] = false;
        int sel[4]; float sw[4]; float wsum = 0.f;
        for (int j = 0; j < 4; j++) {
            int bi = -1; float bv = -1.f;
            for (int e = 0; e < E_NUM; e++)
                if (!used[e] && pe[e] > bv) { bv = pe[e]; bi = e; }
            used[bi] = true; sel[j] = bi; sw[j] = bv; wsum += bv;
        }
        for (int j = 0; j < 4; j++) {
            int e = sel[j];
            int pos = atomicAdd(&g_cnt[e], 1);
            g_tok[e * T_TOK + pos] = t;
            g_texp[t * 4 + j] = e;
            g_trow[t * 4 + j] = pos;
            g_twt [t * 4 + j] = sw[j] / wsum;
        }
    }
}

// ---------------- final sum (fp16 down planes) ----------------
__global__ void __launch_bounds__(256) final_sum(float* __restrict__ out) {
    int t = blockIdx.x;
    int e0 = g_texp[t * 4 + 0], e1 = g_texp[t * 4 + 1], e2 = g_texp[t * 4 + 2], e3 = g_texp[t * 4 + 3];
    int r0 = g_trow[t * 4 + 0], r1 = g_trow[t * 4 + 1], r2 = g_trow[t * 4 + 2], r3 = g_trow[t * 4 + 3];
    float w0 = g_twt[t * 4 + 0], w1v = g_twt[t * 4 + 1], w2v = g_twt[t * 4 + 2], w3 = g_twt[t * 4 + 3];
    const __half* d0 = c_down + ((size_t)e0 * T_TOK + r0) * H_DIM;
    const __half* d1 = c_down + ((size_t)e1 * T_TOK + r1) * H_DIM;
    const __half* d2 = c_down + ((size_t)e2 * T_TOK + r2) * H_DIM;
    const __half* d3 = c_down + ((size_t)e3 * T_TOK + r3) * H_DIM;
    for (int h = threadIdx.x * 2; h < H_DIM; h += 512) {
        float2 a0 = __half22float2(*(const __half2*)(d0 + h));
        float2 a1 = __half22float2(*(const __half2*)(d1 + h));
        float2 a2 = __half22float2(*(const __half2*)(d2 + h));
        float2 a3 = __half22float2(*(const __half2*)(d3 + h));
        float* o = out + (size_t)t * H_DIM + h;
        o[0] += w0 * a0.x + w1v * a1.x + w2v * a2.x + w3 * a3.x;
        o[1] += w0 * a0.y + w1v * a1.y + w2v * a2.y + w3 * a3.y;
    }
}

// ---------------- launch ----------------
extern "C" void kernel_launch(void* const* d_in, const int* in_sizes, int n_in,
                              void* d_out, int out_size) {
    (void)in_sizes; (void)n_in; (void)out_size;
    const float* hidden  = (const float*)d_in[0];
    const float* ln1_w   = (const float*)d_in[2];
    const float* ln2_w   = (const float*)d_in[3];
    const float* q_w     = (const float*)d_in[4];
    const float* kv_w    = (const float*)d_in[5];
    const float* o_w     = (const float*)d_in[6];
    const float* gate_w  = (const float*)d_in[7];
    const float* w1      = (const float*)d_in[8];
    const float* w2      = (const float*)d_in[9];
    const float* sh_gu_w = (const float*)d_in[10];
    const float* sh_dn_w = (const float*)d_in[11];
    float* out = (float*)d_out;

    static cudaStream_t s1 = nullptr, s2 = nullptr;
    static cudaEvent_t ev[14];
    if (!s1) {
        cudaStreamCreateWithFlags(&s1, cudaStreamNonBlocking);
        cudaStreamCreateWithFlags(&s2, cudaStreamNonBlocking);
        for (int i = 0; i < 14; i++) cudaEventCreateWithFlags(&ev[i], cudaEventDisableTiming);
    }

    float *pHid, *pX2;
    cudaGetSymbolAddress((void**)&pHid, g_hid);
    cudaGetSymbolAddress((void**)&pX2, g_X2);

    __half *Xh, *qkvo, *ath, *X2h, *guh, *sah, *down;
    __half *qkvw, *owh, *w1h, *w2h, *sgh, *sdh;
    cudaGetSymbolAddress((void**)&Xh, c_Xh);
    cudaGetSymbolAddress((void**)&qkvo, c_qkvo);
    cudaGetSymbolAddress((void**)&ath, c_ath);
    cudaGetSymbolAddress((void**)&X2h, c_X2h);
    cudaGetSymbolAddress((void**)&guh, c_guh);
    cudaGetSymbolAddress((void**)&sah, c_sah);
    cudaGetSymbolAddress((void**)&down, c_down);
    cudaGetSymbolAddress((void**)&qkvw, c_qkvw);
    cudaGetSymbolAddress((void**)&owh, c_owh);
    cudaGetSymbolAddress((void**)&w1h, c_w1h);
    cudaGetSymbolAddress((void**)&w2h, c_w2h);
    cudaGetSymbolAddress((void**)&sgh, c_sgh);
    cudaGetSymbolAddress((void**)&sdh, c_sdh);

    cudaFuncSetAttribute(attn_mma, cudaFuncAttributeMaxDynamicSharedMemorySize, ATTN_SMEM);
    cudaFuncSetAttribute(gemm_h<0, 1>, cudaFuncAttributeMaxDynamicSharedMemorySize, GSMEM_BYTES);
    cudaFuncSetAttribute(gemm_h<0, 2>, cudaFuncAttributeMaxDynamicSharedMemorySize, GSMEM_BYTES);
    cudaFuncSetAttribute(gemm_h<0, 3>, cudaFuncAttributeMaxDynamicSharedMemorySize, GSMEM_BYTES);
    cudaFuncSetAttribute(gemm_h<1, 3>, cudaFuncAttributeMaxDynamicSharedMemorySize, GSMEM_BYTES);
    cudaFuncSetAttribute(gemm_h<2, 2>, cudaFuncAttributeMaxDynamicSharedMemorySize, GSMEM_BYTES);

    // fork side streams
    cudaEventRecord(ev[0], 0);
    cudaStreamWaitEvent(s1, ev[0], 0);
    cudaStreamWaitEvent(s2, ev[0], 0);

    // s1: conversions — KV FIRST (unblocks the long KV-GEMM earliest), then Q, then the rest
    convKV<<<4096, 256, 0, s1>>>(kv_w);                           cudaEventRecord(ev[2], s1);
    convQ<<<2048, 256, 0, s1>>>(q_w);                             cudaEventRecord(ev[1], s1);
    convW<<<2048, 256, 0, s1>>>(o_w, owh, 2048);                  cudaEventRecord(ev[3], s1);
    convPair<<<E_NUM * TWO_I, 256, 0, s1>>>(w1, w1h, 2048, I_DIM);   cudaEventRecord(ev[4], s1);
    convPair<<<SH2, 256, 0, s1>>>(sh_gu_w, sgh, 2048, SHI_DIM);   cudaEventRecord(ev[5], s1);
    convW<<<E_NUM * H_DIM, 256, 0, s1>>>(w2, w2h, 1408);          cudaEventRecord(ev[6], s1);
    convW<<<H_DIM, 256, 0, s1>>>(sh_dn_w, sdh, 2816);             cudaEventRecord(ev[7], s1);

    // s0: rmsnorm -> fp16 X plane
    rmsnorm_h<<<T_TOK, 256>>>(hidden, ln1_w, nullptr, Xh);
    cudaEventRecord(ev[10], 0);   // X plane ready

    // s2: KV projection (columns 2048..6143 of c_qkvo) — long pole, starts earliest
    cudaStreamWaitEvent(s2, ev[10], 0);
    cudaStreamWaitEvent(s2, ev[2], 0);
    gemm_h<0, 2><<<dim3(32, 16, 1), 256, GSMEM_BYTES, s2>>>(
        Xh, 0LL, 2048, qkvw + (size_t)2048 * 2048, 0LL,
        qkvo + 2048, 0LL, 6144, T_TOK, 2048, nullptr, 0);
    cudaEventRecord(ev[11], s2);

    // s0: Q projection (columns 0..2047 of c_qkvo)
    cudaStreamWaitEvent(0, ev[1], 0);
    gemm_h<0, 2><<<dim3(16, 16, 1), 256, GSMEM_BYTES>>>(
        Xh, 0LL, 2048, qkvw, 0LL, qkvo, 0LL, 6144, T_TOK, 2048, nullptr, 0);

    // s0: attention (needs Q + KV)
    cudaStreamWaitEvent(0, ev[11], 0);
    attn_mma<<<dim3(16, 32), 256, ATTN_SMEM>>>();

    // s0: hid = attn @ o_w^T + hidden
    cudaStreamWaitEvent(0, ev[3], 0);
    gemm_h<0, 1><<<dim3(16, 16, 1), 256, GSMEM_BYTES>>>(
        ath, 0LL, 2048, owh, 0LL, pHid, 0LL, H_DIM, T_TOK, 2048, hidden, H_DIM);
    rmsnorm_h<<<T_TOK, 256>>>(pHid, ln2_w, pX2, X2h);
    cudaEventRecord(ev[8], 0);

    // s2: routed branch
    cudaStreamWaitEvent(s2, ev[8], 0);
    zero_cnt<<<1, 32, 0, s2>>>();
    gate_kernel<<<T_TOK, 512, 0, s2>>>(gate_w);
    cudaStreamWaitEvent(s2, ev[4], 0);
    gemm_h<1, 3><<<dim3(22, 16, E_NUM), 256, GSMEM_BYTES, s2>>>(
        X2h, 0LL, 2048, w1h, (long long)TWO_I * H_DIM,
        guh, (long long)T_TOK * I_DIM, I_DIM, 0, 2048, nullptr, 0);
    cudaStreamWaitEvent(s2, ev[6], 0);
    gemm_h<2, 2><<<dim3(16, 16, E_NUM), 256, GSMEM_BYTES, s2>>>(
        guh, (long long)T_TOK * I_DIM, 1408, w2h, (long long)H_DIM * I_DIM,
        down, (long long)T_TOK * H_DIM, H_DIM, 0, 1408, nullptr, 0);
    cudaEventRecord(ev[9], s2);

    // s0: shared branch
    cudaStreamWaitEvent(0, ev[5], 0);
    gemm_h<0, 3><<<dim3(44, 16, 1), 256, GSMEM_BYTES>>>(
        X2h, 0LL, 2048, sgh, 0LL, sah, 0LL, SHI_DIM, T_TOK, 2048, nullptr, 0);
    cudaStreamWaitEvent(0, ev[7], 0);
    gemm_h<0, 1><<<dim3(16, 16, 1), 256, GSMEM_BYTES>>>(
        sah, 0LL, 2816, sdh, 0LL, out, 0LL, H_DIM, T_TOK, 2816, pHid, H_DIM);

    // join routed, final combine
    cudaStreamWaitEvent(0, ev[9], 0);
    final_sum<<<T_TOK, 256>>>(out);
}